// round 5
// baseline (speedup 1.0000x reference)
#include <cuda_runtime.h>
#include <math.h>

#define BB   2
#define NN   2048
#define HH   256
#define NH   8
#define HD   32
#define WIN  32
#define WLEN 65
#define BN   (BB*NN)                       /* 4096 rows */
#define AOFF ((size_t)BB*NN*4*HH)          /* x_final elements = 4194304 */

// ---------------- scratch (static device globals; no allocation) ------------
__device__ __align__(16) float g_q[BN*HH];
__device__ __align__(16) float g_k[BN*HH];
__device__ __align__(16) float g_v[BN*HH];
__device__ __align__(16) float g_vd[BN*HH];
__device__ __align__(16) float g_vn[BN*HH];
__device__ __align__(16) float g_xout[BN*HH];
__device__ __align__(16) float g_vaggr[BN*3*HH];

// ---------------- kernel 1: fused q/k/v projection --------------------------
// 16 rows per block, 256 threads; thread t owns output column t for all rows.
__global__ __launch_bounds__(256) void qkv_kernel(
    const float* __restrict__ x,
    const float* __restrict__ Wq, const float* __restrict__ bq,
    const float* __restrict__ Wk, const float* __restrict__ bk,
    const float* __restrict__ Wv, const float* __restrict__ bv)
{
    __shared__ __align__(16) float xs[16][HH];
    const int t  = threadIdx.x;
    const int rb = blockIdx.x * 16;
#pragma unroll
    for (int r = 0; r < 16; r++)
        xs[r][t] = x[((size_t)(rb + r) * 4) * HH + t];   // x[:, :, 0, :]
    __syncthreads();

    float aq[16], ak[16], av[16];
#pragma unroll
    for (int r = 0; r < 16; r++) { aq[r] = 0.f; ak[r] = 0.f; av[r] = 0.f; }

    for (int k = 0; k < HH; k += 4) {
        float wq0 = Wq[(k+0)*HH+t], wq1 = Wq[(k+1)*HH+t],
              wq2 = Wq[(k+2)*HH+t], wq3 = Wq[(k+3)*HH+t];
        float wk0 = Wk[(k+0)*HH+t], wk1 = Wk[(k+1)*HH+t],
              wk2 = Wk[(k+2)*HH+t], wk3 = Wk[(k+3)*HH+t];
        float wv0 = Wv[(k+0)*HH+t], wv1 = Wv[(k+1)*HH+t],
              wv2 = Wv[(k+2)*HH+t], wv3 = Wv[(k+3)*HH+t];
#pragma unroll
        for (int r = 0; r < 16; r++) {
            float4 xv = *reinterpret_cast<const float4*>(&xs[r][k]);
            aq[r] = fmaf(xv.w,wq3, fmaf(xv.z,wq2, fmaf(xv.y,wq1, fmaf(xv.x,wq0, aq[r]))));
            ak[r] = fmaf(xv.w,wk3, fmaf(xv.z,wk2, fmaf(xv.y,wk1, fmaf(xv.x,wk0, ak[r]))));
            av[r] = fmaf(xv.w,wv3, fmaf(xv.z,wv2, fmaf(xv.y,wv1, fmaf(xv.x,wv0, av[r]))));
        }
    }
    const float bqv = bq[t], bkv = bk[t], bvv = bv[t];
#pragma unroll
    for (int r = 0; r < 16; r++) {
        size_t o = (size_t)(rb + r) * HH + t;
        g_q[o] = aq[r] + bqv;
        g_k[o] = ak[r] + bkv;
        g_v[o] = av[r] + bvv;
    }
}

// ---------------- kernel 2: vec_dot (via Wvec) + vec_norm -------------------
// 8 rows per block, 256 threads.
__global__ __launch_bounds__(256) void vec_kernel(
    const float* __restrict__ x, const float* __restrict__ Wvec)
{
    __shared__ __align__(16) float vs[8][3][HH];
    const int t  = threadIdx.x;
    const int rb = blockIdx.x * 8;
#pragma unroll
    for (int r = 0; r < 8; r++)
#pragma unroll
        for (int c = 0; c < 3; c++)
            vs[r][c][t] = x[((size_t)(rb + r) * 4 + 1 + c) * HH + t];
    __syncthreads();

    float a1[8][3], a2[8][3];
#pragma unroll
    for (int r = 0; r < 8; r++)
#pragma unroll
        for (int c = 0; c < 3; c++) { a1[r][c] = 0.f; a2[r][c] = 0.f; }

    for (int k = 0; k < HH; k += 4) {
        float w10 = Wvec[(k+0)*2*HH + t],      w11 = Wvec[(k+1)*2*HH + t],
              w12 = Wvec[(k+2)*2*HH + t],      w13 = Wvec[(k+3)*2*HH + t];
        float w20 = Wvec[(k+0)*2*HH + HH + t], w21 = Wvec[(k+1)*2*HH + HH + t],
              w22 = Wvec[(k+2)*2*HH + HH + t], w23 = Wvec[(k+3)*2*HH + HH + t];
#pragma unroll
        for (int r = 0; r < 8; r++)
#pragma unroll
            for (int c = 0; c < 3; c++) {
                float4 vv = *reinterpret_cast<const float4*>(&vs[r][c][k]);
                a1[r][c] = fmaf(vv.w,w13, fmaf(vv.z,w12, fmaf(vv.y,w11, fmaf(vv.x,w10, a1[r][c]))));
                a2[r][c] = fmaf(vv.w,w23, fmaf(vv.z,w22, fmaf(vv.y,w21, fmaf(vv.x,w20, a2[r][c]))));
            }
    }
#pragma unroll
    for (int r = 0; r < 8; r++) {
        float vd = a1[r][0]*a2[r][0] + a1[r][1]*a2[r][1] + a1[r][2]*a2[r][2];
        float v0 = vs[r][0][t], v1 = vs[r][1][t], v2 = vs[r][2][t];
        float vn = sqrtf(v0*v0 + v1*v1 + v2*v2);
        size_t o = (size_t)(rb + r) * HH + t;
        g_vd[o] = vd;
        g_vn[o] = vn;
    }
}

// ---------------- kernel 3: sliding-window attention ------------------------
// grid (N/64, heads, B), 128 threads (4 warps). Each warp owns 16 queries.
// Phase 1: warp-collective scores+softmax (K tile in smem, weights to smem+gmem).
// Phase 2: 8-query register blocking, lane owns 4 dims of [v(32)|vec(96)].
__global__ __launch_bounds__(128) void attn_kernel(
    const float* __restrict__ x, float* __restrict__ out)
{
    __shared__ float ks[128][33];      // padded to kill bank conflicts
    __shared__ float qs[64][32];
    __shared__ float ws[4][16][66];
    const int tid  = threadIdx.x;
    const int lane = tid & 31;
    const int wp   = tid >> 5;
    const int i0   = blockIdx.x * 64;
    const int hh   = blockIdx.y;
    const int b    = blockIdx.z;
    const int jb   = i0 - WIN;

    const float* kg = g_k + (size_t)b * NN * HH + hh * HD;
    for (int idx = tid; idx < 128 * 32; idx += 128) {
        int r = idx >> 5, dd = idx & 31, j = jb + r;
        ks[r][dd] = ((unsigned)j < NN) ? kg[(size_t)j * HH + dd] : 0.f;
    }
    const float* qg = g_q + ((size_t)b * NN + i0) * HH + hh * HD;
    for (int idx = tid; idx < 64 * 32; idx += 128) {
        int r = idx >> 5, dd = idx & 31;
        qs[r][dd] = qg[(size_t)r * HH + dd];
    }
    __syncthreads();

    const float scale = 0.17677669529663687f;   // 1/sqrt(32)
    for (int ql = 0; ql < 16; ql++) {
        const int q = wp * 16 + ql;
        const int i = i0 + q;
        float s0, s1, s2 = -1e30f;
        {
            float acc = 0.f; const int row = q + lane;
#pragma unroll
            for (int dd = 0; dd < 32; dd++) acc = fmaf(qs[q][dd], ks[row][dd], acc);
            s0 = acc * scale;
        }
        {
            float acc = 0.f; const int row = q + lane + 32;
#pragma unroll
            for (int dd = 0; dd < 32; dd++) acc = fmaf(qs[q][dd], ks[row][dd], acc);
            s1 = acc * scale;
        }
        if (lane == 0) {
            float acc = 0.f; const int row = q + 64;
#pragma unroll
            for (int dd = 0; dd < 32; dd++) acc = fmaf(qs[q][dd], ks[row][dd], acc);
            s2 = acc * scale;
        }
        float mx = fmaxf(fmaxf(s0, s1), s2);
#pragma unroll
        for (int o = 16; o; o >>= 1) mx = fmaxf(mx, __shfl_xor_sync(0xffffffffu, mx, o));
        float e0 = expf(s0 - mx), e1 = expf(s1 - mx);
        float e2 = (lane == 0) ? expf(s2 - mx) : 0.f;
        float sm = e0 + e1 + e2;
#pragma unroll
        for (int o = 16; o; o >>= 1) sm += __shfl_xor_sync(0xffffffffu, sm, o);
        float inv = 1.f / sm;
        float p0 = e0 * inv, p1 = e1 * inv, p2 = e2 * inv;
        float* ab = out + AOFF + (((size_t)(b * NH + hh)) * NN + i) * WLEN;
        ab[lane]      = p0;
        ab[lane + 32] = p1;
        if (lane == 0) ab[64] = p2;
        ws[wp][ql][lane]      = p0;
        ws[wp][ql][lane + 32] = p1;
        if (lane == 0) ws[wp][ql][64] = p2;
    }
    __syncwarp();

    const float* vgp = g_v + (size_t)b * NN * HH + hh * HD;
    const bool isv = (lane < 8);
    int c = 0, ddv = 0;
    if (!isv) { c = (lane - 8) >> 3; ddv = (lane - 8 - c * 8) * 4; }

    for (int g = 0; g < 2; g++) {
        const int qb = wp * 16 + g * 8;
        float4 acc[8];
#pragma unroll
        for (int g8 = 0; g8 < 8; g8++) acc[g8] = make_float4(0.f, 0.f, 0.f, 0.f);

        for (int r = 0; r < 72; r++) {
            const int row = qb + r;
            const int j   = jb + row;
            float4 val = make_float4(0.f, 0.f, 0.f, 0.f);
            if ((unsigned)j < NN) {
                if (isv)
                    val = *reinterpret_cast<const float4*>(&vgp[(size_t)j * HH + lane * 4]);
                else
                    val = *reinterpret_cast<const float4*>(
                        &x[(((size_t)(b * NN + j)) * 4 + 1 + c) * HH + hh * HD + ddv]);
            }
#pragma unroll
            for (int g8 = 0; g8 < 8; g8++) {
                const int jj = r - g8;
                if (jj >= 0 && jj < WLEN) {
                    const float w = ws[wp][g * 8 + g8][jj];
                    acc[g8].x = fmaf(w, val.x, acc[g8].x);
                    acc[g8].y = fmaf(w, val.y, acc[g8].y);
                    acc[g8].z = fmaf(w, val.z, acc[g8].z);
                    acc[g8].w = fmaf(w, val.w, acc[g8].w);
                }
            }
        }
#pragma unroll
        for (int g8 = 0; g8 < 8; g8++) {
            const int i = i0 + qb + g8;
            if (isv)
                *reinterpret_cast<float4*>(
                    &g_xout[((size_t)b * NN + i) * HH + hh * HD + lane * 4]) = acc[g8];
            else
                *reinterpret_cast<float4*>(
                    &g_vaggr[(((size_t)(b * NN + i)) * 3 + c) * HH + hh * HD + ddv]) = acc[g8];
        }
    }
}

// ---------------- kernel 4: o = x_out @ Wo + bo ; x_updated -----------------
__global__ __launch_bounds__(256) void out_kernel(
    const float* __restrict__ Wo, const float* __restrict__ bo,
    float* __restrict__ out)
{
    __shared__ __align__(16) float xo[16][HH];
    const int t  = threadIdx.x;
    const int rb = blockIdx.x * 16;
#pragma unroll
    for (int r = 0; r < 16; r++)
        xo[r][t] = g_xout[(size_t)(rb + r) * HH + t];
    __syncthreads();

    float a0[16], a1[16], a2[16];
#pragma unroll
    for (int r = 0; r < 16; r++) { a0[r] = 0.f; a1[r] = 0.f; a2[r] = 0.f; }

    for (int k = 0; k < HH; k += 4) {
        float u0 = Wo[(k+0)*768 + t],       u1 = Wo[(k+1)*768 + t],
              u2 = Wo[(k+2)*768 + t],       u3 = Wo[(k+3)*768 + t];
        float v0 = Wo[(k+0)*768 + 256 + t], v1 = Wo[(k+1)*768 + 256 + t],
              v2 = Wo[(k+2)*768 + 256 + t], v3 = Wo[(k+3)*768 + 256 + t];
        float w0 = Wo[(k+0)*768 + 512 + t], w1 = Wo[(k+1)*768 + 512 + t],
              w2 = Wo[(k+2)*768 + 512 + t], w3 = Wo[(k+3)*768 + 512 + t];
#pragma unroll
        for (int r = 0; r < 16; r++) {
            float4 xv = *reinterpret_cast<const float4*>(&xo[r][k]);
            a0[r] = fmaf(xv.w,u3, fmaf(xv.z,u2, fmaf(xv.y,u1, fmaf(xv.x,u0, a0[r]))));
            a1[r] = fmaf(xv.w,v3, fmaf(xv.z,v2, fmaf(xv.y,v1, fmaf(xv.x,v0, a1[r]))));
            a2[r] = fmaf(xv.w,w3, fmaf(xv.z,w2, fmaf(xv.y,w1, fmaf(xv.x,w0, a2[r]))));
        }
    }
    const float b0 = bo[t], b1 = bo[256 + t], b2 = bo[512 + t];
#pragma unroll
    for (int r = 0; r < 16; r++) {
        size_t n  = (size_t)(rb + r);
        float vd = g_vd[n * HH + t];
        float vn = g_vn[n * HH + t];
        out[(n * 4) * HH + t] = vd * (a0[r] + b0) + vn * (a1[r] + b1) + (a2[r] + b2);
    }
}

// ---------------- kernel 5: gate + vec_combined -----------------------------
__global__ __launch_bounds__(256) void gate_kernel(
    const float* __restrict__ x,
    const float* __restrict__ Wg, const float* __restrict__ bg,
    const float* __restrict__ alpha_dot, const float* __restrict__ alpha_norm,
    float* __restrict__ out)
{
    __shared__ __align__(16) float vds[16][HH];
    __shared__ __align__(16) float vns[16][HH];
    const int t  = threadIdx.x;
    const int rb = blockIdx.x * 16;
#pragma unroll
    for (int r = 0; r < 16; r++) {
        vds[r][t] = g_vd[(size_t)(rb + r) * HH + t];
        vns[r][t] = g_vn[(size_t)(rb + r) * HH + t];
    }
    __syncthreads();

    float ag1[16], ag2[16];
#pragma unroll
    for (int r = 0; r < 16; r++) { ag1[r] = 0.f; ag2[r] = 0.f; }

    for (int k = 0; k < HH; k += 4) {
        float a0 = Wg[(k+0)*HH + t],        a1w = Wg[(k+1)*HH + t],
              a2w = Wg[(k+2)*HH + t],       a3 = Wg[(k+3)*HH + t];
        float b0 = Wg[(HH+k+0)*HH + t],     b1 = Wg[(HH+k+1)*HH + t],
              b2 = Wg[(HH+k+2)*HH + t],     b3 = Wg[(HH+k+3)*HH + t];
#pragma unroll
        for (int r = 0; r < 16; r++) {
            float4 v1 = *reinterpret_cast<const float4*>(&vds[r][k]);
            float4 v2 = *reinterpret_cast<const float4*>(&vns[r][k]);
            ag1[r] = fmaf(v1.w,a3, fmaf(v1.z,a2w, fmaf(v1.y,a1w, fmaf(v1.x,a0, ag1[r]))));
            ag2[r] = fmaf(v2.w,b3, fmaf(v2.z,b2,  fmaf(v2.y,b1,  fmaf(v2.x,b0, ag2[r]))));
        }
    }
    const float ad = *alpha_dot, an = *alpha_norm, bgt = bg[t];
#pragma unroll
    for (int r = 0; r < 16; r++) {
        size_t n = (size_t)(rb + r);
        float z    = ad * ag1[r] + an * ag2[r] + bgt;
        float gate = 1.f / (1.f + expf(-z));
#pragma unroll
        for (int c = 0; c < 3; c++) {
            size_t oi = ((n * 4) + 1 + c) * HH + t;
            out[oi] = gate * g_vaggr[((n * 3) + c) * HH + t] + x[oi];
        }
    }
}

// ---------------- launch ----------------------------------------------------
extern "C" void kernel_launch(void* const* d_in, const int* in_sizes, int n_in,
                              void* d_out, int out_size)
{
    const float* x    = (const float*)d_in[0];
    const float* Wq   = (const float*)d_in[1];
    const float* bq   = (const float*)d_in[2];
    const float* Wk   = (const float*)d_in[3];
    const float* bk   = (const float*)d_in[4];
    const float* Wv   = (const float*)d_in[5];
    const float* bv   = (const float*)d_in[6];
    const float* Wo   = (const float*)d_in[7];
    const float* bo   = (const float*)d_in[8];
    const float* Wvec = (const float*)d_in[9];
    const float* ad   = (const float*)d_in[10];
    const float* an   = (const float*)d_in[11];
    const float* Wg   = (const float*)d_in[12];
    const float* bg   = (const float*)d_in[13];
    float* out = (float*)d_out;

    qkv_kernel <<<BN / 16, 256>>>(x, Wq, bq, Wk, bk, Wv, bv);
    vec_kernel <<<BN / 8,  256>>>(x, Wvec);
    attn_kernel<<<dim3(NN / 64, NH, BB), 128>>>(x, out);
    out_kernel <<<BN / 16, 256>>>(Wo, bo, out);
    gate_kernel<<<BN / 16, 256>>>(x, Wg, bg, ad, an, out);
}

// round 6
// speedup vs baseline: 1.7936x; 1.7936x over previous
#include <cuda_runtime.h>
#include <math.h>

#define BB   2
#define NN   2048
#define HH   256
#define NH   8
#define HD   32
#define WIN  32
#define WLEN 65
#define BN   (BB*NN)                       /* 4096 rows */
#define AOFF ((size_t)BB*NN*4*HH)          /* x_final elements = 4194304 */

// ---------------- scratch (static device globals; no allocation) ------------
__device__ __align__(16) float g_q[BN*HH];
__device__ __align__(16) float g_k[BN*HH];
__device__ __align__(16) float g_v[BN*HH];
__device__ __align__(16) float g_vd[BN*HH];
__device__ __align__(16) float g_vn[BN*HH];
__device__ __align__(16) float g_xout[BN*HH];
__device__ __align__(16) float g_vaggr[BN*3*HH];

// ---------------- tf32 mma helpers ------------------------------------------
__device__ __forceinline__ unsigned f2tf(float x) {
    unsigned u; asm("cvt.rna.tf32.f32 %0, %1;" : "=r"(u) : "f"(x)); return u;
}
__device__ __forceinline__ void mma_tf32(float* c, const unsigned* a, const unsigned* b) {
    asm volatile("mma.sync.aligned.m16n8k8.row.col.f32.tf32.tf32.f32 "
        "{%0,%1,%2,%3}, {%4,%5,%6,%7}, {%8,%9}, {%0,%1,%2,%3};"
        : "+f"(c[0]), "+f"(c[1]), "+f"(c[2]), "+f"(c[3])
        : "r"(a[0]), "r"(a[1]), "r"(a[2]), "r"(a[3]), "r"(b[0]), "r"(b[1]));
}

// ---------------- kernel 1: q/k/v projection (tf32 MMA) ----------------------
// grid (64, 12): y selects weight (0-3:Wq, 4-7:Wk, 8-11:Wv) and 64-col tile.
// BM=64, BN=64, BK=32; 4 warps 2x2, warp tile 32x32.
__global__ __launch_bounds__(128) void qkv_mma(
    const float* __restrict__ x,
    const float* __restrict__ Wq, const float* __restrict__ bq,
    const float* __restrict__ Wk, const float* __restrict__ bk,
    const float* __restrict__ Wv, const float* __restrict__ bv)
{
    __shared__ unsigned As[2][64][36];
    __shared__ unsigned Bs[2][32][72];
    const int t = threadIdx.x, lane = t & 31, wp = t >> 5;
    const int g = lane >> 2, tg = lane & 3;
    const int wm = wp >> 1, wn = wp & 1;
    const int rb = blockIdx.x * 64;
    const int nt = blockIdx.y;
    const float *W, *bias; float* outp;
    if (nt < 4)      { W = Wq; bias = bq; outp = g_q; }
    else if (nt < 8) { W = Wk; bias = bk; outp = g_k; }
    else             { W = Wv; bias = bv; outp = g_v; }
    const int cb = (nt & 3) * 64;

    float C[2][4][4];
#pragma unroll
    for (int mi = 0; mi < 2; mi++)
#pragma unroll
        for (int ni = 0; ni < 4; ni++)
#pragma unroll
            for (int e = 0; e < 4; e++) C[mi][ni][e] = 0.f;

    // load chunk 0
#pragma unroll
    for (int i = 0; i < 4; i++) {
        int idx = t + i * 128; int r = idx >> 3, c4 = (idx & 7) * 4;
        float4 v = *(const float4*)(x + (size_t)(rb + r) * 1024 + c4);
        As[0][r][c4] = f2tf(v.x); As[0][r][c4+1] = f2tf(v.y);
        As[0][r][c4+2] = f2tf(v.z); As[0][r][c4+3] = f2tf(v.w);
    }
#pragma unroll
    for (int i = 0; i < 4; i++) {
        int idx = t + i * 128; int r = idx >> 4, c4 = (idx & 15) * 4;
        float4 v = *(const float4*)(W + (size_t)r * 256 + cb + c4);
        Bs[0][r][c4] = f2tf(v.x); Bs[0][r][c4+1] = f2tf(v.y);
        Bs[0][r][c4+2] = f2tf(v.z); Bs[0][r][c4+3] = f2tf(v.w);
    }
    __syncthreads();

    float4 sA[4], sB[4];
    for (int kc = 0; kc < 8; kc++) {
        const int buf = kc & 1;
        const int k0n = (kc + 1) * 32;
        if (kc < 7) {
#pragma unroll
            for (int i = 0; i < 4; i++) {
                int idx = t + i * 128; int r = idx >> 3, c4 = (idx & 7) * 4;
                sA[i] = *(const float4*)(x + (size_t)(rb + r) * 1024 + k0n + c4);
            }
#pragma unroll
            for (int i = 0; i < 4; i++) {
                int idx = t + i * 128; int r = idx >> 4, c4 = (idx & 15) * 4;
                sB[i] = *(const float4*)(W + (size_t)(k0n + r) * 256 + cb + c4);
            }
        }
#pragma unroll
        for (int kk = 0; kk < 32; kk += 8) {
            unsigned a[2][4], b[4][2];
#pragma unroll
            for (int mi = 0; mi < 2; mi++) {
                int row = wm * 32 + mi * 16;
                a[mi][0] = As[buf][row + g][kk + tg];
                a[mi][1] = As[buf][row + g + 8][kk + tg];
                a[mi][2] = As[buf][row + g][kk + tg + 4];
                a[mi][3] = As[buf][row + g + 8][kk + tg + 4];
            }
#pragma unroll
            for (int ni = 0; ni < 4; ni++) {
                int col = wn * 32 + ni * 8 + g;
                b[ni][0] = Bs[buf][kk + tg][col];
                b[ni][1] = Bs[buf][kk + tg + 4][col];
            }
#pragma unroll
            for (int mi = 0; mi < 2; mi++)
#pragma unroll
                for (int ni = 0; ni < 4; ni++)
                    mma_tf32(C[mi][ni], a[mi], b[ni]);
        }
        if (kc < 7) {
            __syncthreads();
            const int nb = buf ^ 1;
#pragma unroll
            for (int i = 0; i < 4; i++) {
                int idx = t + i * 128; int r = idx >> 3, c4 = (idx & 7) * 4;
                As[nb][r][c4] = f2tf(sA[i].x); As[nb][r][c4+1] = f2tf(sA[i].y);
                As[nb][r][c4+2] = f2tf(sA[i].z); As[nb][r][c4+3] = f2tf(sA[i].w);
            }
#pragma unroll
            for (int i = 0; i < 4; i++) {
                int idx = t + i * 128; int r = idx >> 4, c4 = (idx & 15) * 4;
                Bs[nb][r][c4] = f2tf(sB[i].x); Bs[nb][r][c4+1] = f2tf(sB[i].y);
                Bs[nb][r][c4+2] = f2tf(sB[i].z); Bs[nb][r][c4+3] = f2tf(sB[i].w);
            }
            __syncthreads();
        }
    }
    // epilogue: add bias, store
#pragma unroll
    for (int mi = 0; mi < 2; mi++)
#pragma unroll
        for (int ni = 0; ni < 4; ni++) {
            int row = rb + wm * 32 + mi * 16 + g;
            int col = cb + wn * 32 + ni * 8 + 2 * tg;
            float b0 = bias[col], b1 = bias[col + 1];
            *(float2*)(outp + (size_t)row * 256 + col) =
                make_float2(C[mi][ni][0] + b0, C[mi][ni][1] + b1);
            *(float2*)(outp + (size_t)(row + 8) * 256 + col) =
                make_float2(C[mi][ni][2] + b0, C[mi][ni][3] + b1);
        }
}

// ---------------- kernel 2: vec_proj (tf32 MMA) -> vec_dot; + vec_norm ------
// A = vec rows (b,n,c) [12288 x 256]; B = Wvec two col-sets (t, t+256).
// BM=48 (16 (b,n) groups), BN=32 per set, BK=32. 6 warps (3m x 2n), warp 16x16.
__global__ __launch_bounds__(192) void vec_mma(
    const float* __restrict__ x, const float* __restrict__ Wvec)
{
    __shared__ unsigned As[2][48][36];
    __shared__ unsigned Bs[2][2][32][40];
    __shared__ float pr[48][36];
    const int t = threadIdx.x, lane = t & 31, wp = t >> 5;
    const int g = lane >> 2, tg = lane & 3;
    const int wm = wp % 3, wn = wp / 3;
    const int rb3 = blockIdx.x * 48, bn0 = blockIdx.x * 16;
    const int n0 = blockIdx.y * 32;
    const bool ny0 = (blockIdx.y == 0);

    float C[2][2][4];
#pragma unroll
    for (int s = 0; s < 2; s++)
#pragma unroll
        for (int ni = 0; ni < 2; ni++)
#pragma unroll
            for (int e = 0; e < 4; e++) C[s][ni][e] = 0.f;

    // load chunk 0
#pragma unroll
    for (int i = 0; i < 2; i++) {
        int idx = t + i * 192; int r = idx >> 3, c4 = (idx & 7) * 4;
        int R = rb3 + r, bn = R / 3, cch = R - bn * 3;
        float4 v = *(const float4*)(x + ((size_t)bn * 4 + 1 + cch) * 256 + c4);
        As[0][r][c4] = f2tf(v.x); As[0][r][c4+1] = f2tf(v.y);
        As[0][r][c4+2] = f2tf(v.z); As[0][r][c4+3] = f2tf(v.w);
    }
#pragma unroll
    for (int i = 0; i < 3; i++) {
        int idx = t + i * 192;
        if (idx < 512) {
            int s = idx >> 8, rem = idx & 255, r = rem >> 3, c4 = (rem & 7) * 4;
            float4 v = *(const float4*)(Wvec + (size_t)r * 512 + s * 256 + n0 + c4);
            Bs[0][s][r][c4] = f2tf(v.x); Bs[0][s][r][c4+1] = f2tf(v.y);
            Bs[0][s][r][c4+2] = f2tf(v.z); Bs[0][s][r][c4+3] = f2tf(v.w);
        }
    }
    __syncthreads();

    float4 sA[2], sB[3];
    for (int kc = 0; kc < 8; kc++) {
        const int buf = kc & 1;
        const int k0n = (kc + 1) * 32;
        // vec_norm (over original vec components = A's K dim), only n-tile 0
        if (ny0) {
            for (int idx = t; idx < 512; idx += 192) {
                int G = idx >> 5, kk = idx & 31;
                float v0 = __uint_as_float(As[buf][3*G][kk]);
                float v1 = __uint_as_float(As[buf][3*G+1][kk]);
                float v2 = __uint_as_float(As[buf][3*G+2][kk]);
                g_vn[(size_t)(bn0 + G) * 256 + kc * 32 + kk] =
                    sqrtf(v0*v0 + v1*v1 + v2*v2);
            }
        }
        if (kc < 7) {
#pragma unroll
            for (int i = 0; i < 2; i++) {
                int idx = t + i * 192; int r = idx >> 3, c4 = (idx & 7) * 4;
                int R = rb3 + r, bn = R / 3, cch = R - bn * 3;
                sA[i] = *(const float4*)(x + ((size_t)bn * 4 + 1 + cch) * 256 + k0n + c4);
            }
#pragma unroll
            for (int i = 0; i < 3; i++) {
                int idx = t + i * 192;
                if (idx < 512) {
                    int s = idx >> 8, rem = idx & 255, r = rem >> 3, c4 = (rem & 7) * 4;
                    sB[i] = *(const float4*)(Wvec + (size_t)(k0n + r) * 512 + s * 256 + n0 + c4);
                }
            }
        }
#pragma unroll
        for (int kk = 0; kk < 32; kk += 8) {
            unsigned a[4], b[2][2][2];
            {
                int row = wm * 16;
                a[0] = As[buf][row + g][kk + tg];
                a[1] = As[buf][row + g + 8][kk + tg];
                a[2] = As[buf][row + g][kk + tg + 4];
                a[3] = As[buf][row + g + 8][kk + tg + 4];
            }
#pragma unroll
            for (int s = 0; s < 2; s++)
#pragma unroll
                for (int ni = 0; ni < 2; ni++) {
                    int col = wn * 16 + ni * 8 + g;
                    b[s][ni][0] = Bs[buf][s][kk + tg][col];
                    b[s][ni][1] = Bs[buf][s][kk + tg + 4][col];
                }
#pragma unroll
            for (int s = 0; s < 2; s++)
#pragma unroll
                for (int ni = 0; ni < 2; ni++)
                    mma_tf32(C[s][ni], a, b[s][ni]);
        }
        if (kc < 7) {
            __syncthreads();
            const int nb = buf ^ 1;
#pragma unroll
            for (int i = 0; i < 2; i++) {
                int idx = t + i * 192; int r = idx >> 3, c4 = (idx & 7) * 4;
                As[nb][r][c4] = f2tf(sA[i].x); As[nb][r][c4+1] = f2tf(sA[i].y);
                As[nb][r][c4+2] = f2tf(sA[i].z); As[nb][r][c4+3] = f2tf(sA[i].w);
            }
#pragma unroll
            for (int i = 0; i < 3; i++) {
                int idx = t + i * 192;
                if (idx < 512) {
                    int s = idx >> 8, rem = idx & 255, r = rem >> 3, c4 = (rem & 7) * 4;
                    Bs[nb][s][r][c4] = f2tf(sB[i].x); Bs[nb][s][r][c4+1] = f2tf(sB[i].y);
                    Bs[nb][s][r][c4+2] = f2tf(sB[i].z); Bs[nb][s][r][c4+3] = f2tf(sB[i].w);
                }
            }
            __syncthreads();
        }
    }
    // elementwise product vec1*vec2 into pr, then reduce over the 3 channels
#pragma unroll
    for (int ni = 0; ni < 2; ni++) {
        int r0 = wm * 16 + g, c0 = wn * 16 + ni * 8 + 2 * tg;
        pr[r0][c0]       = C[0][ni][0] * C[1][ni][0];
        pr[r0][c0 + 1]   = C[0][ni][1] * C[1][ni][1];
        pr[r0 + 8][c0]   = C[0][ni][2] * C[1][ni][2];
        pr[r0 + 8][c0+1] = C[0][ni][3] * C[1][ni][3];
    }
    __syncthreads();
    for (int idx = t; idx < 512; idx += 192) {
        int G = idx >> 5, tt = idx & 31;
        g_vd[(size_t)(bn0 + G) * 256 + n0 + tt] =
            pr[3*G][tt] + pr[3*G+1][tt] + pr[3*G+2][tt];
    }
}

// ---------------- kernel 3: sliding-window attention (unchanged, fp32) ------
__global__ __launch_bounds__(128) void attn_kernel(
    const float* __restrict__ x, float* __restrict__ out)
{
    __shared__ float ks[128][33];
    __shared__ float qs[64][32];
    __shared__ float ws[4][16][66];
    const int tid  = threadIdx.x;
    const int lane = tid & 31;
    const int wp   = tid >> 5;
    const int i0   = blockIdx.x * 64;
    const int hh   = blockIdx.y;
    const int b    = blockIdx.z;
    const int jb   = i0 - WIN;

    const float* kg = g_k + (size_t)b * NN * HH + hh * HD;
    for (int idx = tid; idx < 128 * 32; idx += 128) {
        int r = idx >> 5, dd = idx & 31, j = jb + r;
        ks[r][dd] = ((unsigned)j < NN) ? kg[(size_t)j * HH + dd] : 0.f;
    }
    const float* qg = g_q + ((size_t)b * NN + i0) * HH + hh * HD;
    for (int idx = tid; idx < 64 * 32; idx += 128) {
        int r = idx >> 5, dd = idx & 31;
        qs[r][dd] = qg[(size_t)r * HH + dd];
    }
    __syncthreads();

    const float scale = 0.17677669529663687f;
    for (int ql = 0; ql < 16; ql++) {
        const int q = wp * 16 + ql;
        const int i = i0 + q;
        float s0, s1, s2 = -1e30f;
        {
            float acc = 0.f; const int row = q + lane;
#pragma unroll
            for (int dd = 0; dd < 32; dd++) acc = fmaf(qs[q][dd], ks[row][dd], acc);
            s0 = acc * scale;
        }
        {
            float acc = 0.f; const int row = q + lane + 32;
#pragma unroll
            for (int dd = 0; dd < 32; dd++) acc = fmaf(qs[q][dd], ks[row][dd], acc);
            s1 = acc * scale;
        }
        if (lane == 0) {
            float acc = 0.f; const int row = q + 64;
#pragma unroll
            for (int dd = 0; dd < 32; dd++) acc = fmaf(qs[q][dd], ks[row][dd], acc);
            s2 = acc * scale;
        }
        float mx = fmaxf(fmaxf(s0, s1), s2);
#pragma unroll
        for (int o = 16; o; o >>= 1) mx = fmaxf(mx, __shfl_xor_sync(0xffffffffu, mx, o));
        float e0 = expf(s0 - mx), e1 = expf(s1 - mx);
        float e2 = (lane == 0) ? expf(s2 - mx) : 0.f;
        float sm = e0 + e1 + e2;
#pragma unroll
        for (int o = 16; o; o >>= 1) sm += __shfl_xor_sync(0xffffffffu, sm, o);
        float inv = 1.f / sm;
        float p0 = e0 * inv, p1 = e1 * inv, p2 = e2 * inv;
        float* ab = out + AOFF + (((size_t)(b * NH + hh)) * NN + i) * WLEN;
        ab[lane]      = p0;
        ab[lane + 32] = p1;
        if (lane == 0) ab[64] = p2;
        ws[wp][ql][lane]      = p0;
        ws[wp][ql][lane + 32] = p1;
        if (lane == 0) ws[wp][ql][64] = p2;
    }
    __syncwarp();

    const float* vgp = g_v + (size_t)b * NN * HH + hh * HD;
    const bool isv = (lane < 8);
    int c = 0, ddv = 0;
    if (!isv) { c = (lane - 8) >> 3; ddv = (lane - 8 - c * 8) * 4; }

    for (int gg = 0; gg < 2; gg++) {
        const int qb = wp * 16 + gg * 8;
        float4 acc[8];
#pragma unroll
        for (int g8 = 0; g8 < 8; g8++) acc[g8] = make_float4(0.f, 0.f, 0.f, 0.f);

        for (int r = 0; r < 72; r++) {
            const int row = qb + r;
            const int j   = jb + row;
            float4 val = make_float4(0.f, 0.f, 0.f, 0.f);
            if ((unsigned)j < NN) {
                if (isv)
                    val = *reinterpret_cast<const float4*>(&vgp[(size_t)j * HH + lane * 4]);
                else
                    val = *reinterpret_cast<const float4*>(
                        &x[(((size_t)(b * NN + j)) * 4 + 1 + c) * HH + hh * HD + ddv]);
            }
#pragma unroll
            for (int g8 = 0; g8 < 8; g8++) {
                const int jj = r - g8;
                if (jj >= 0 && jj < WLEN) {
                    const float w = ws[wp][gg * 8 + g8][jj];
                    acc[g8].x = fmaf(w, val.x, acc[g8].x);
                    acc[g8].y = fmaf(w, val.y, acc[g8].y);
                    acc[g8].z = fmaf(w, val.z, acc[g8].z);
                    acc[g8].w = fmaf(w, val.w, acc[g8].w);
                }
            }
        }
#pragma unroll
        for (int g8 = 0; g8 < 8; g8++) {
            const int i = i0 + qb + g8;
            if (isv)
                *reinterpret_cast<float4*>(
                    &g_xout[((size_t)b * NN + i) * HH + hh * HD + lane * 4]) = acc[g8];
            else
                *reinterpret_cast<float4*>(
                    &g_vaggr[(((size_t)(b * NN + i)) * 3 + c) * HH + hh * HD + ddv]) = acc[g8];
        }
    }
}

// ---------------- kernel 4: o = x_out @ Wo + bo ; x_updated (tf32 MMA) ------
// BM=32, BN=32 per set, 3 col-sets (o1,o2,o3). 4 warps 2x2, warp 16x16.
__global__ __launch_bounds__(128) void out_mma(
    const float* __restrict__ Wo, const float* __restrict__ bo,
    float* __restrict__ out)
{
    __shared__ unsigned As[2][32][36];
    __shared__ unsigned Bs[2][3][32][40];
    const int t = threadIdx.x, lane = t & 31, wp = t >> 5;
    const int g = lane >> 2, tg = lane & 3;
    const int wm = wp >> 1, wn = wp & 1;
    const int rb = blockIdx.x * 32;
    const int cb = blockIdx.y * 32;

    float C[3][2][4];
#pragma unroll
    for (int s = 0; s < 3; s++)
#pragma unroll
        for (int ni = 0; ni < 2; ni++)
#pragma unroll
            for (int e = 0; e < 4; e++) C[s][ni][e] = 0.f;

#pragma unroll
    for (int i = 0; i < 2; i++) {
        int idx = t + i * 128; int r = idx >> 3, c4 = (idx & 7) * 4;
        float4 v = *(const float4*)(g_xout + (size_t)(rb + r) * 256 + c4);
        As[0][r][c4] = f2tf(v.x); As[0][r][c4+1] = f2tf(v.y);
        As[0][r][c4+2] = f2tf(v.z); As[0][r][c4+3] = f2tf(v.w);
    }
#pragma unroll
    for (int i = 0; i < 6; i++) {
        int idx = t + i * 128;
        int s = idx >> 8, rem = idx & 255, r = rem >> 3, c4 = (rem & 7) * 4;
        float4 v = *(const float4*)(Wo + (size_t)r * 768 + s * 256 + cb + c4);
        Bs[0][s][r][c4] = f2tf(v.x); Bs[0][s][r][c4+1] = f2tf(v.y);
        Bs[0][s][r][c4+2] = f2tf(v.z); Bs[0][s][r][c4+3] = f2tf(v.w);
    }
    __syncthreads();

    float4 sA[2], sB[6];
    for (int kc = 0; kc < 8; kc++) {
        const int buf = kc & 1;
        const int k0n = (kc + 1) * 32;
        if (kc < 7) {
#pragma unroll
            for (int i = 0; i < 2; i++) {
                int idx = t + i * 128; int r = idx >> 3, c4 = (idx & 7) * 4;
                sA[i] = *(const float4*)(g_xout + (size_t)(rb + r) * 256 + k0n + c4);
            }
#pragma unroll
            for (int i = 0; i < 6; i++) {
                int idx = t + i * 128;
                int s = idx >> 8, rem = idx & 255, r = rem >> 3, c4 = (rem & 7) * 4;
                sB[i] = *(const float4*)(Wo + (size_t)(k0n + r) * 768 + s * 256 + cb + c4);
            }
        }
#pragma unroll
        for (int kk = 0; kk < 32; kk += 8) {
            unsigned a[4], b[3][2][2];
            {
                int row = wm * 16;
                a[0] = As[buf][row + g][kk + tg];
                a[1] = As[buf][row + g + 8][kk + tg];
                a[2] = As[buf][row + g][kk + tg + 4];
                a[3] = As[buf][row + g + 8][kk + tg + 4];
            }
#pragma unroll
            for (int s = 0; s < 3; s++)
#pragma unroll
                for (int ni = 0; ni < 2; ni++) {
                    int col = wn * 16 + ni * 8 + g;
                    b[s][ni][0] = Bs[buf][s][kk + tg][col];
                    b[s][ni][1] = Bs[buf][s][kk + tg + 4][col];
                }
#pragma unroll
            for (int s = 0; s < 3; s++)
#pragma unroll
                for (int ni = 0; ni < 2; ni++)
                    mma_tf32(C[s][ni], a, b[s][ni]);
        }
        if (kc < 7) {
            __syncthreads();
            const int nb = buf ^ 1;
#pragma unroll
            for (int i = 0; i < 2; i++) {
                int idx = t + i * 128; int r = idx >> 3, c4 = (idx & 7) * 4;
                As[nb][r][c4] = f2tf(sA[i].x); As[nb][r][c4+1] = f2tf(sA[i].y);
                As[nb][r][c4+2] = f2tf(sA[i].z); As[nb][r][c4+3] = f2tf(sA[i].w);
            }
#pragma unroll
            for (int i = 0; i < 6; i++) {
                int idx = t + i * 128;
                int s = idx >> 8, rem = idx & 255, r = rem >> 3, c4 = (rem & 7) * 4;
                Bs[nb][s][r][c4] = f2tf(sB[i].x); Bs[nb][s][r][c4+1] = f2tf(sB[i].y);
                Bs[nb][s][r][c4+2] = f2tf(sB[i].z); Bs[nb][s][r][c4+3] = f2tf(sB[i].w);
            }
            __syncthreads();
        }
    }
    // epilogue: x_updated = vd*o1 + vn*o2 + o3
#pragma unroll
    for (int ni = 0; ni < 2; ni++) {
        int col = cb + wn * 16 + ni * 8 + 2 * tg;
        float b0 = bo[col],       b1 = bo[col + 1];
        float b2 = bo[col + 256], b3 = bo[col + 257];
        float b4 = bo[col + 512], b5 = bo[col + 513];
#pragma unroll
        for (int hf = 0; hf < 2; hf++) {
            int row = rb + wm * 16 + g + hf * 8;
            int e = hf * 2;
            float2 vd = *(const float2*)(g_vd + (size_t)row * 256 + col);
            float2 vn = *(const float2*)(g_vn + (size_t)row * 256 + col);
            float rx = vd.x * (C[0][ni][e]   + b0) + vn.x * (C[1][ni][e]   + b2) + (C[2][ni][e]   + b4);
            float ry = vd.y * (C[0][ni][e+1] + b1) + vn.y * (C[1][ni][e+1] + b3) + (C[2][ni][e+1] + b5);
            *(float2*)(out + (size_t)row * 1024 + col) = make_float2(rx, ry);
        }
    }
}

// ---------------- kernel 5: gate GEMM + vec_combined (tf32 MMA) -------------
// A = [ad*vd | an*vn] (K=512), B = Wg. BM=32, BN=64. 4 warps 2x2, warp 16x32.
__global__ __launch_bounds__(128) void gate_mma(
    const float* __restrict__ x,
    const float* __restrict__ Wg, const float* __restrict__ bg,
    const float* __restrict__ alpha_dot, const float* __restrict__ alpha_norm,
    float* __restrict__ out)
{
    __shared__ unsigned As[2][32][36];
    __shared__ unsigned Bs[2][32][72];
    const int t = threadIdx.x, lane = t & 31, wp = t >> 5;
    const int g = lane >> 2, tg = lane & 3;
    const int wm = wp >> 1, wn = wp & 1;
    const int rb = blockIdx.x * 32;
    const int cb = blockIdx.y * 64;
    const float adv = *alpha_dot, anv = *alpha_norm;

    float C[4][4];
#pragma unroll
    for (int ni = 0; ni < 4; ni++)
#pragma unroll
        for (int e = 0; e < 4; e++) C[ni][e] = 0.f;

    // chunk 0 (always in vd half)
#pragma unroll
    for (int i = 0; i < 2; i++) {
        int idx = t + i * 128; int r = idx >> 3, c4 = (idx & 7) * 4;
        float4 v = *(const float4*)(g_vd + (size_t)(rb + r) * 256 + c4);
        As[0][r][c4] = f2tf(adv * v.x); As[0][r][c4+1] = f2tf(adv * v.y);
        As[0][r][c4+2] = f2tf(adv * v.z); As[0][r][c4+3] = f2tf(adv * v.w);
    }
#pragma unroll
    for (int i = 0; i < 4; i++) {
        int idx = t + i * 128; int r = idx >> 4, c4 = (idx & 15) * 4;
        float4 v = *(const float4*)(Wg + (size_t)r * 256 + cb + c4);
        Bs[0][r][c4] = f2tf(v.x); Bs[0][r][c4+1] = f2tf(v.y);
        Bs[0][r][c4+2] = f2tf(v.z); Bs[0][r][c4+3] = f2tf(v.w);
    }
    __syncthreads();

    float4 sA[2], sB[4];
    for (int kc = 0; kc < 16; kc++) {
        const int buf = kc & 1;
        const int k0n = (kc + 1) * 32;
        float scl = 0.f;
        if (kc < 15) {
            const float* src = (k0n < 256) ? g_vd : g_vn;
            scl = (k0n < 256) ? adv : anv;
            const int kk0 = k0n & 255;
#pragma unroll
            for (int i = 0; i < 2; i++) {
                int idx = t + i * 128; int r = idx >> 3, c4 = (idx & 7) * 4;
                sA[i] = *(const float4*)(src + (size_t)(rb + r) * 256 + kk0 + c4);
            }
#pragma unroll
            for (int i = 0; i < 4; i++) {
                int idx = t + i * 128; int r = idx >> 4, c4 = (idx & 15) * 4;
                sB[i] = *(const float4*)(Wg + (size_t)(k0n + r) * 256 + cb + c4);
            }
        }
#pragma unroll
        for (int kk = 0; kk < 32; kk += 8) {
            unsigned a[4], b[4][2];
            {
                int row = wm * 16;
                a[0] = As[buf][row + g][kk + tg];
                a[1] = As[buf][row + g + 8][kk + tg];
                a[2] = As[buf][row + g][kk + tg + 4];
                a[3] = As[buf][row + g + 8][kk + tg + 4];
            }
#pragma unroll
            for (int ni = 0; ni < 4; ni++) {
                int col = wn * 32 + ni * 8 + g;
                b[ni][0] = Bs[buf][kk + tg][col];
                b[ni][1] = Bs[buf][kk + tg + 4][col];
            }
#pragma unroll
            for (int ni = 0; ni < 4; ni++)
                mma_tf32(C[ni], a, b[ni]);
        }
        if (kc < 15) {
            __syncthreads();
            const int nb = buf ^ 1;
#pragma unroll
            for (int i = 0; i < 2; i++) {
                int idx = t + i * 128; int r = idx >> 3, c4 = (idx & 7) * 4;
                As[nb][r][c4] = f2tf(scl * sA[i].x); As[nb][r][c4+1] = f2tf(scl * sA[i].y);
                As[nb][r][c4+2] = f2tf(scl * sA[i].z); As[nb][r][c4+3] = f2tf(scl * sA[i].w);
            }
#pragma unroll
            for (int i = 0; i < 4; i++) {
                int idx = t + i * 128; int r = idx >> 4, c4 = (idx & 15) * 4;
                Bs[nb][r][c4] = f2tf(sB[i].x); Bs[nb][r][c4+1] = f2tf(sB[i].y);
                Bs[nb][r][c4+2] = f2tf(sB[i].z); Bs[nb][r][c4+3] = f2tf(sB[i].w);
            }
            __syncthreads();
        }
    }
    // epilogue: gate = sigmoid(z); out_vec = gate*vaggr + vec
#pragma unroll
    for (int ni = 0; ni < 4; ni++) {
        int col = cb + wn * 32 + ni * 8 + 2 * tg;
        float bg0 = bg[col], bg1 = bg[col + 1];
#pragma unroll
        for (int hf = 0; hf < 2; hf++) {
            int row = rb + wm * 16 + g + hf * 8;
            int e = hf * 2;
            float g0 = 1.f / (1.f + expf(-(C[ni][e]   + bg0)));
            float g1 = 1.f / (1.f + expf(-(C[ni][e+1] + bg1)));
#pragma unroll
            for (int c = 0; c < 3; c++) {
                float2 va = *(const float2*)(g_vaggr + ((size_t)row * 3 + c) * 256 + col);
                size_t oi = ((size_t)row * 4 + 1 + c) * 256 + col;
                float2 xv = *(const float2*)(x + oi);
                *(float2*)(out + oi) = make_float2(g0 * va.x + xv.x, g1 * va.y + xv.y);
            }
        }
    }
}

// ---------------- launch ----------------------------------------------------
extern "C" void kernel_launch(void* const* d_in, const int* in_sizes, int n_in,
                              void* d_out, int out_size)
{
    const float* x    = (const float*)d_in[0];
    const float* Wq   = (const float*)d_in[1];
    const float* bq   = (const float*)d_in[2];
    const float* Wk   = (const float*)d_in[3];
    const float* bk   = (const float*)d_in[4];
    const float* Wv   = (const float*)d_in[5];
    const float* bv   = (const float*)d_in[6];
    const float* Wo   = (const float*)d_in[7];
    const float* bo   = (const float*)d_in[8];
    const float* Wvec = (const float*)d_in[9];
    const float* ad   = (const float*)d_in[10];
    const float* an   = (const float*)d_in[11];
    const float* Wg   = (const float*)d_in[12];
    const float* bg   = (const float*)d_in[13];
    float* out = (float*)d_out;

    qkv_mma <<<dim3(BN / 64, 12), 128>>>(x, Wq, bq, Wk, bk, Wv, bv);
    vec_mma <<<dim3(BN / 16, 8), 192>>>(x, Wvec);
    attn_kernel<<<dim3(NN / 64, NH, BB), 128>>>(x, out);
    out_mma <<<dim3(BN / 32, 8), 128>>>(Wo, bo, out);
    gate_mma<<<dim3(BN / 32, 4), 128>>>(x, Wg, bg, ad, an, out);
}

// round 8
// speedup vs baseline: 2.0935x; 1.1672x over previous
#include <cuda_runtime.h>
#include <cuda_bf16.h>
#include <math.h>

#define BB   2
#define NN   2048
#define HH   256
#define NH   8
#define HD   32
#define WIN  32
#define WLEN 65
#define BN   (BB*NN)                       /* 4096 rows */
#define AOFF ((size_t)BB*NN*4*HH)          /* x_final elements = 4194304 */

// ---------------- scratch (static device globals; no allocation) ------------
__device__ __align__(16) float g_q[BN*HH];
__device__ __align__(16) float g_k[BN*HH];
__device__ __align__(16) float g_v[BN*HH];
__device__ __align__(16) float g_vd[BN*HH];
__device__ __align__(16) float g_vn[BN*HH];
__device__ __align__(16) float g_xout[BN*HH];
__device__ __align__(16) float g_vaggr[BN*3*HH];

// ---------------- bf16 mma helpers ------------------------------------------
// pack two fp32 into bf16x2 (lo = first elem in memory order)
__device__ __forceinline__ unsigned pk(float lo, float hi) {
    unsigned r; asm("cvt.rn.bf16x2.f32 %0, %1, %2;" : "=r"(r) : "f"(hi), "f"(lo));
    return r;
}
__device__ __forceinline__ unsigned su(const void* p) {
    return (unsigned)__cvta_generic_to_shared(p);
}
__device__ __forceinline__ void ldsm4(unsigned* r, unsigned a) {
    asm volatile("ldmatrix.sync.aligned.m8n8.x4.shared.b16 {%0,%1,%2,%3},[%4];"
        : "=r"(r[0]), "=r"(r[1]), "=r"(r[2]), "=r"(r[3]) : "r"(a));
}
__device__ __forceinline__ void ldsm4t(unsigned* r, unsigned a) {
    asm volatile("ldmatrix.sync.aligned.m8n8.x4.trans.shared.b16 {%0,%1,%2,%3},[%4];"
        : "=r"(r[0]), "=r"(r[1]), "=r"(r[2]), "=r"(r[3]) : "r"(a));
}
__device__ __forceinline__ void mma_bf16(float* c, const unsigned* a, const unsigned* b) {
    asm volatile("mma.sync.aligned.m16n8k16.row.col.f32.bf16.bf16.f32 "
        "{%0,%1,%2,%3},{%4,%5,%6,%7},{%8,%9},{%0,%1,%2,%3};"
        : "+f"(c[0]), "+f"(c[1]), "+f"(c[2]), "+f"(c[3])
        : "r"(a[0]), "r"(a[1]), "r"(a[2]), "r"(a[3]), "r"(b[0]), "r"(b[1]));
}

// ---------------- kernel 1: q/k/v projection (bf16 MMA + ldmatrix) ----------
// grid (64, 12): y selects weight (0-3:Wq, 4-7:Wk, 8-11:Wv) + 64-col tile.
// BM=64, BN=64, BK=32. 4 warps 2x2, warp tile 32x32.
__global__ __launch_bounds__(128) void qkv_mma(
    const float* __restrict__ x,
    const float* __restrict__ Wq, const float* __restrict__ bq,
    const float* __restrict__ Wk, const float* __restrict__ bk,
    const float* __restrict__ Wv, const float* __restrict__ bv)
{
    __shared__ unsigned As[2][64][20];      // 64 rows x 32 bf16 (pad->40)
    __shared__ unsigned Bs[2][32][36];      // 32 k-rows x 64 bf16 (pad->72)
    const int t = threadIdx.x, lane = t & 31, wp = t >> 5;
    const int g = lane >> 2, tg = lane & 3;
    const int wm = wp >> 1, wn = wp & 1;
    const int tl = lane >> 3, trow = lane & 7;
    const int aRow  = (tl & 1) * 8 + trow;     // row within 16-row ldsm tile
    const int aColW = (tl >> 1) * 4;           // word offset within 16-bf16 span
    const int rb = blockIdx.x * 64;
    const int nt = blockIdx.y;
    const float *W, *bias; float* outp;
    if (nt < 4)      { W = Wq; bias = bq; outp = g_q; }
    else if (nt < 8) { W = Wk; bias = bk; outp = g_k; }
    else             { W = Wv; bias = bv; outp = g_v; }
    const int cb = (nt & 3) * 64;

    float C[2][4][4];
#pragma unroll
    for (int mi = 0; mi < 2; mi++)
#pragma unroll
        for (int nj = 0; nj < 4; nj++)
#pragma unroll
            for (int e = 0; e < 4; e++) C[mi][nj][e] = 0.f;

    // stage 0
#pragma unroll
    for (int i = 0; i < 4; i++) {
        int idx = t + i * 128; int r = idx >> 3, cw = (idx & 7) * 2;
        float4 v = *(const float4*)(x + (size_t)(rb + r) * 1024 + cw * 2);
        As[0][r][cw] = pk(v.x, v.y); As[0][r][cw + 1] = pk(v.z, v.w);
    }
#pragma unroll
    for (int i = 0; i < 4; i++) {
        int idx = t + i * 128; int r = idx >> 4, cw = (idx & 15) * 2;
        float4 v = *(const float4*)(W + (size_t)r * 256 + cb + cw * 2);
        Bs[0][r][cw] = pk(v.x, v.y); Bs[0][r][cw + 1] = pk(v.z, v.w);
    }
    __syncthreads();

    float4 sA[4], sB[4];
    for (int kc = 0; kc < 8; kc++) {
        const int buf = kc & 1;
        const int k0n = (kc + 1) * 32;
        if (kc < 7) {
#pragma unroll
            for (int i = 0; i < 4; i++) {
                int idx = t + i * 128; int r = idx >> 3, cw = (idx & 7) * 2;
                sA[i] = *(const float4*)(x + (size_t)(rb + r) * 1024 + k0n + cw * 2);
            }
#pragma unroll
            for (int i = 0; i < 4; i++) {
                int idx = t + i * 128; int r = idx >> 4, cw = (idx & 15) * 2;
                sB[i] = *(const float4*)(W + (size_t)(k0n + r) * 256 + cb + cw * 2);
            }
        }
#pragma unroll
        for (int kk = 0; kk < 32; kk += 16) {
            const int kkW = kk >> 1;
            unsigned a[2][4], bfr[2][4];
#pragma unroll
            for (int mi = 0; mi < 2; mi++)
                ldsm4(a[mi], su(&As[buf][wm * 32 + mi * 16 + aRow][aColW + kkW]));
#pragma unroll
            for (int ns = 0; ns < 2; ns++)
                ldsm4t(bfr[ns], su(&Bs[buf][kk + aRow][wn * 16 + ns * 8 + aColW]));
#pragma unroll
            for (int mi = 0; mi < 2; mi++)
#pragma unroll
                for (int nj = 0; nj < 4; nj++)
                    mma_bf16(C[mi][nj], a[mi], &bfr[nj >> 1][(nj & 1) * 2]);
        }
        if (kc < 7) {
            __syncthreads();
            const int nb = buf ^ 1;
#pragma unroll
            for (int i = 0; i < 4; i++) {
                int idx = t + i * 128; int r = idx >> 3, cw = (idx & 7) * 2;
                As[nb][r][cw] = pk(sA[i].x, sA[i].y); As[nb][r][cw + 1] = pk(sA[i].z, sA[i].w);
            }
#pragma unroll
            for (int i = 0; i < 4; i++) {
                int idx = t + i * 128; int r = idx >> 4, cw = (idx & 15) * 2;
                Bs[nb][r][cw] = pk(sB[i].x, sB[i].y); Bs[nb][r][cw + 1] = pk(sB[i].z, sB[i].w);
            }
            __syncthreads();
        }
    }
#pragma unroll
    for (int mi = 0; mi < 2; mi++)
#pragma unroll
        for (int nj = 0; nj < 4; nj++) {
            int row = rb + wm * 32 + mi * 16 + g;
            int col = cb + wn * 32 + nj * 8 + 2 * tg;
            float b0 = bias[col], b1 = bias[col + 1];
            *(float2*)(outp + (size_t)row * 256 + col) =
                make_float2(C[mi][nj][0] + b0, C[mi][nj][1] + b1);
            *(float2*)(outp + (size_t)(row + 8) * 256 + col) =
                make_float2(C[mi][nj][2] + b0, C[mi][nj][3] + b1);
        }
}

// ---------------- kernel 2: vec_proj (bf16 MMA) -> vec_dot; + fp32 vec_norm -
// A = vec rows (b,n,c) [12288 x 256]; B = Wvec two col-sets.
// BM=48, BN=32/set, BK=32. 6 warps (3m x 2n), warp 16x16.
__global__ __launch_bounds__(192) void vec_mma(
    const float* __restrict__ x, const float* __restrict__ Wvec)
{
    __shared__ unsigned As[2][48][20];
    __shared__ unsigned Bs[2][2][32][20];
    __shared__ float pr[48][36];
    const int t = threadIdx.x, lane = t & 31, wp = t >> 5;
    const int g = lane >> 2, tg = lane & 3;
    const int wm = wp % 3, wn = wp / 3;
    const int tl = lane >> 3, trow = lane & 7;
    const int aRow  = (tl & 1) * 8 + trow;
    const int aColW = (tl >> 1) * 4;
    const int rb3 = blockIdx.x * 48, bn0 = blockIdx.x * 16;
    const int n0 = blockIdx.y * 32;

    // fp32 vec_norm (exact inputs), only the y==0 column of blocks
    if (blockIdx.y == 0) {
        for (int idx = t; idx < 16 * 256; idx += 192) {
            int G = idx >> 8, tt = idx & 255;
            size_t base = ((size_t)(bn0 + G) * 4 + 1) * 256 + tt;
            float v0 = x[base], v1 = x[base + 256], v2 = x[base + 512];
            g_vn[(size_t)(bn0 + G) * 256 + tt] = sqrtf(v0*v0 + v1*v1 + v2*v2);
        }
    }

    float C[2][2][4];
#pragma unroll
    for (int s = 0; s < 2; s++)
#pragma unroll
        for (int ni = 0; ni < 2; ni++)
#pragma unroll
            for (int e = 0; e < 4; e++) C[s][ni][e] = 0.f;

    // stage 0
#pragma unroll
    for (int i = 0; i < 2; i++) {
        int idx = t + i * 192; int r = idx >> 3, cw = (idx & 7) * 2;
        int R = rb3 + r, bn = R / 3, cch = R - bn * 3;
        float4 v = *(const float4*)(x + ((size_t)bn * 4 + 1 + cch) * 256 + cw * 2);
        As[0][r][cw] = pk(v.x, v.y); As[0][r][cw + 1] = pk(v.z, v.w);
    }
#pragma unroll
    for (int i = 0; i < 3; i++) {
        int idx = t + i * 192;
        if (idx < 512) {
            int s = idx >> 8, rem = idx & 255, r = rem >> 3, cw = (rem & 7) * 2;
            float4 v = *(const float4*)(Wvec + (size_t)r * 512 + s * 256 + n0 + cw * 2);
            Bs[0][s][r][cw] = pk(v.x, v.y); Bs[0][s][r][cw + 1] = pk(v.z, v.w);
        }
    }
    __syncthreads();

    float4 sA[2], sB[3];
    for (int kc = 0; kc < 8; kc++) {
        const int buf = kc & 1;
        const int k0n = (kc + 1) * 32;
        if (kc < 7) {
#pragma unroll
            for (int i = 0; i < 2; i++) {
                int idx = t + i * 192; int r = idx >> 3, cw = (idx & 7) * 2;
                int R = rb3 + r, bn = R / 3, cch = R - bn * 3;
                sA[i] = *(const float4*)(x + ((size_t)bn * 4 + 1 + cch) * 256 + k0n + cw * 2);
            }
#pragma unroll
            for (int i = 0; i < 3; i++) {
                int idx = t + i * 192;
                if (idx < 512) {
                    int s = idx >> 8, rem = idx & 255, r = rem >> 3, cw = (rem & 7) * 2;
                    sB[i] = *(const float4*)(Wvec + (size_t)(k0n + r) * 512 + s * 256 + n0 + cw * 2);
                }
            }
        }
#pragma unroll
        for (int kk = 0; kk < 32; kk += 16) {
            const int kkW = kk >> 1;
            unsigned a[4], bfr[2][4];
            ldsm4(a, su(&As[buf][wm * 16 + aRow][aColW + kkW]));
#pragma unroll
            for (int s = 0; s < 2; s++)
                ldsm4t(bfr[s], su(&Bs[buf][s][kk + aRow][wn * 8 + aColW]));
#pragma unroll
            for (int s = 0; s < 2; s++)
#pragma unroll
                for (int ni = 0; ni < 2; ni++)
                    mma_bf16(C[s][ni], a, &bfr[s][ni * 2]);
        }
        if (kc < 7) {
            __syncthreads();
            const int nb = buf ^ 1;
#pragma unroll
            for (int i = 0; i < 2; i++) {
                int idx = t + i * 192; int r = idx >> 3, cw = (idx & 7) * 2;
                As[nb][r][cw] = pk(sA[i].x, sA[i].y); As[nb][r][cw + 1] = pk(sA[i].z, sA[i].w);
            }
#pragma unroll
            for (int i = 0; i < 3; i++) {
                int idx = t + i * 192;
                if (idx < 512) {
                    int s = idx >> 8, rem = idx & 255, r = rem >> 3, cw = (rem & 7) * 2;
                    Bs[nb][s][r][cw] = pk(sB[i].x, sB[i].y); Bs[nb][s][r][cw + 1] = pk(sB[i].z, sB[i].w);
                }
            }
            __syncthreads();
        }
    }
    // elementwise product vec1*vec2, then reduce over 3 channels
#pragma unroll
    for (int ni = 0; ni < 2; ni++) {
        int r0 = wm * 16 + g, c0 = wn * 16 + ni * 8 + 2 * tg;
        pr[r0][c0]       = C[0][ni][0] * C[1][ni][0];
        pr[r0][c0 + 1]   = C[0][ni][1] * C[1][ni][1];
        pr[r0 + 8][c0]   = C[0][ni][2] * C[1][ni][2];
        pr[r0 + 8][c0+1] = C[0][ni][3] * C[1][ni][3];
    }
    __syncthreads();
    for (int idx = t; idx < 512; idx += 192) {
        int G = idx >> 5, tt = idx & 31;
        g_vd[(size_t)(bn0 + G) * 256 + n0 + tt] =
            pr[3*G][tt] + pr[3*G+1][tt] + pr[3*G+2][tt];
    }
}

// ---------------- kernel 3: sliding-window attention (fp32, unchanged) ------
__global__ __launch_bounds__(128) void attn_kernel(
    const float* __restrict__ x, float* __restrict__ out)
{
    __shared__ float ks[128][33];
    __shared__ float qs[64][32];
    __shared__ float ws[4][16][66];
    const int tid  = threadIdx.x;
    const int lane = tid & 31;
    const int wp   = tid >> 5;
    const int i0   = blockIdx.x * 64;
    const int hh   = blockIdx.y;
    const int b    = blockIdx.z;
    const int jb   = i0 - WIN;

    const float* kg = g_k + (size_t)b * NN * HH + hh * HD;
    for (int idx = tid; idx < 128 * 32; idx += 128) {
        int r = idx >> 5, dd = idx & 31, j = jb + r;
        ks[r][dd] = ((unsigned)j < NN) ? kg[(size_t)j * HH + dd] : 0.f;
    }
    const float* qg = g_q + ((size_t)b * NN + i0) * HH + hh * HD;
    for (int idx = tid; idx < 64 * 32; idx += 128) {
        int r = idx >> 5, dd = idx & 31;
        qs[r][dd] = qg[(size_t)r * HH + dd];
    }
    __syncthreads();

    const float scale = 0.17677669529663687f;
    for (int ql = 0; ql < 16; ql++) {
        const int q = wp * 16 + ql;
        const int i = i0 + q;
        float s0, s1, s2 = -1e30f;
        {
            float acc = 0.f; const int row = q + lane;
#pragma unroll
            for (int dd = 0; dd < 32; dd++) acc = fmaf(qs[q][dd], ks[row][dd], acc);
            s0 = acc * scale;
        }
        {
            float acc = 0.f; const int row = q + lane + 32;
#pragma unroll
            for (int dd = 0; dd < 32; dd++) acc = fmaf(qs[q][dd], ks[row][dd], acc);
            s1 = acc * scale;
        }
        if (lane == 0) {
            float acc = 0.f; const int row = q + 64;
#pragma unroll
            for (int dd = 0; dd < 32; dd++) acc = fmaf(qs[q][dd], ks[row][dd], acc);
            s2 = acc * scale;
        }
        float mx = fmaxf(fmaxf(s0, s1), s2);
#pragma unroll
        for (int o = 16; o; o >>= 1) mx = fmaxf(mx, __shfl_xor_sync(0xffffffffu, mx, o));
        float e0 = expf(s0 - mx), e1 = expf(s1 - mx);
        float e2 = (lane == 0) ? expf(s2 - mx) : 0.f;
        float sm = e0 + e1 + e2;
#pragma unroll
        for (int o = 16; o; o >>= 1) sm += __shfl_xor_sync(0xffffffffu, sm, o);
        float inv = 1.f / sm;
        float p0 = e0 * inv, p1 = e1 * inv, p2 = e2 * inv;
        float* ab = out + AOFF + (((size_t)(b * NH + hh)) * NN + i) * WLEN;
        ab[lane]      = p0;
        ab[lane + 32] = p1;
        if (lane == 0) ab[64] = p2;
        ws[wp][ql][lane]      = p0;
        ws[wp][ql][lane + 32] = p1;
        if (lane == 0) ws[wp][ql][64] = p2;
    }
    __syncwarp();

    const float* vgp = g_v + (size_t)b * NN * HH + hh * HD;
    const bool isv = (lane < 8);
    int c = 0, ddv = 0;
    if (!isv) { c = (lane - 8) >> 3; ddv = (lane - 8 - c * 8) * 4; }

    for (int gg = 0; gg < 2; gg++) {
        const int qb = wp * 16 + gg * 8;
        float4 acc[8];
#pragma unroll
        for (int g8 = 0; g8 < 8; g8++) acc[g8] = make_float4(0.f, 0.f, 0.f, 0.f);

        for (int r = 0; r < 72; r++) {
            const int row = qb + r;
            const int j   = jb + row;
            float4 val = make_float4(0.f, 0.f, 0.f, 0.f);
            if ((unsigned)j < NN) {
                if (isv)
                    val = *reinterpret_cast<const float4*>(&vgp[(size_t)j * HH + lane * 4]);
                else
                    val = *reinterpret_cast<const float4*>(
                        &x[(((size_t)(b * NN + j)) * 4 + 1 + c) * HH + hh * HD + ddv]);
            }
#pragma unroll
            for (int g8 = 0; g8 < 8; g8++) {
                const int jj = r - g8;
                if (jj >= 0 && jj < WLEN) {
                    const float w = ws[wp][gg * 8 + g8][jj];
                    acc[g8].x = fmaf(w, val.x, acc[g8].x);
                    acc[g8].y = fmaf(w, val.y, acc[g8].y);
                    acc[g8].z = fmaf(w, val.z, acc[g8].z);
                    acc[g8].w = fmaf(w, val.w, acc[g8].w);
                }
            }
        }
#pragma unroll
        for (int g8 = 0; g8 < 8; g8++) {
            const int i = i0 + qb + g8;
            if (isv)
                *reinterpret_cast<float4*>(
                    &g_xout[((size_t)b * NN + i) * HH + hh * HD + lane * 4]) = acc[g8];
            else
                *reinterpret_cast<float4*>(
                    &g_vaggr[(((size_t)(b * NN + i)) * 3 + c) * HH + hh * HD + ddv]) = acc[g8];
        }
    }
}

// ---------------- kernel 4: o = x_out @ Wo + bo ; x_updated (bf16 MMA) ------
// BM=32, BN=32 per set, 3 col-sets. 4 warps 2x2, warp 16x16.
__global__ __launch_bounds__(128) void out_mma(
    const float* __restrict__ Wo, const float* __restrict__ bo,
    float* __restrict__ out)
{
    __shared__ unsigned As[2][32][20];
    __shared__ unsigned Bs[2][3][32][20];
    const int t = threadIdx.x, lane = t & 31, wp = t >> 5;
    const int g = lane >> 2, tg = lane & 3;
    const int wm = wp >> 1, wn = wp & 1;
    const int tl = lane >> 3, trow = lane & 7;
    const int aRow  = (tl & 1) * 8 + trow;
    const int aColW = (tl >> 1) * 4;
    const int rb = blockIdx.x * 32;
    const int cb = blockIdx.y * 32;

    float C[3][2][4];
#pragma unroll
    for (int s = 0; s < 3; s++)
#pragma unroll
        for (int ni = 0; ni < 2; ni++)
#pragma unroll
            for (int e = 0; e < 4; e++) C[s][ni][e] = 0.f;

#pragma unroll
    for (int i = 0; i < 2; i++) {
        int idx = t + i * 128; int r = idx >> 3, cw = (idx & 7) * 2;
        float4 v = *(const float4*)(g_xout + (size_t)(rb + r) * 256 + cw * 2);
        As[0][r][cw] = pk(v.x, v.y); As[0][r][cw + 1] = pk(v.z, v.w);
    }
#pragma unroll
    for (int i = 0; i < 6; i++) {
        int idx = t + i * 128;
        int s = idx >> 8, rem = idx & 255, r = rem >> 3, cw = (rem & 7) * 2;
        float4 v = *(const float4*)(Wo + (size_t)r * 768 + s * 256 + cb + cw * 2);
        Bs[0][s][r][cw] = pk(v.x, v.y); Bs[0][s][r][cw + 1] = pk(v.z, v.w);
    }
    __syncthreads();

    float4 sA[2], sB[6];
    for (int kc = 0; kc < 8; kc++) {
        const int buf = kc & 1;
        const int k0n = (kc + 1) * 32;
        if (kc < 7) {
#pragma unroll
            for (int i = 0; i < 2; i++) {
                int idx = t + i * 128; int r = idx >> 3, cw = (idx & 7) * 2;
                sA[i] = *(const float4*)(g_xout + (size_t)(rb + r) * 256 + k0n + cw * 2);
            }
#pragma unroll
            for (int i = 0; i < 6; i++) {
                int idx = t + i * 128;
                int s = idx >> 8, rem = idx & 255, r = rem >> 3, cw = (rem & 7) * 2;
                sB[i] = *(const float4*)(Wo + (size_t)(k0n + r) * 768 + s * 256 + cb + cw * 2);
            }
        }
#pragma unroll
        for (int kk = 0; kk < 32; kk += 16) {
            const int kkW = kk >> 1;
            unsigned a[4], bfr[3][4];
            ldsm4(a, su(&As[buf][wm * 16 + aRow][aColW + kkW]));
#pragma unroll
            for (int s = 0; s < 3; s++)
                ldsm4t(bfr[s], su(&Bs[buf][s][kk + aRow][wn * 8 + aColW]));
#pragma unroll
            for (int s = 0; s < 3; s++)
#pragma unroll
                for (int ni = 0; ni < 2; ni++)
                    mma_bf16(C[s][ni], a, &bfr[s][ni * 2]);
        }
        if (kc < 7) {
            __syncthreads();
            const int nb = buf ^ 1;
#pragma unroll
            for (int i = 0; i < 2; i++) {
                int idx = t + i * 128; int r = idx >> 3, cw = (idx & 7) * 2;
                As[nb][r][cw] = pk(sA[i].x, sA[i].y); As[nb][r][cw + 1] = pk(sA[i].z, sA[i].w);
            }
#pragma unroll
            for (int i = 0; i < 6; i++) {
                int idx = t + i * 128;
                int s = idx >> 8, rem = idx & 255, r = rem >> 3, cw = (rem & 7) * 2;
                Bs[nb][s][r][cw] = pk(sB[i].x, sB[i].y); Bs[nb][s][r][cw + 1] = pk(sB[i].z, sB[i].w);
            }
            __syncthreads();
        }
    }
    // epilogue: x_updated = vd*o1 + vn*o2 + o3
#pragma unroll
    for (int ni = 0; ni < 2; ni++) {
        int col = cb + wn * 16 + ni * 8 + 2 * tg;
        float b0 = bo[col],       b1 = bo[col + 1];
        float b2 = bo[col + 256], b3 = bo[col + 257];
        float b4 = bo[col + 512], b5 = bo[col + 513];
#pragma unroll
        for (int hf = 0; hf < 2; hf++) {
            int row = rb + wm * 16 + g + hf * 8;
            int e = hf * 2;
            float2 vd = *(const float2*)(g_vd + (size_t)row * 256 + col);
            float2 vn = *(const float2*)(g_vn + (size_t)row * 256 + col);
            float rx = vd.x * (C[0][ni][e]   + b0) + vn.x * (C[1][ni][e]   + b2) + (C[2][ni][e]   + b4);
            float ry = vd.y * (C[0][ni][e+1] + b1) + vn.y * (C[1][ni][e+1] + b3) + (C[2][ni][e+1] + b5);
            *(float2*)(out + (size_t)row * 1024 + col) = make_float2(rx, ry);
        }
    }
}

// ---------------- kernel 5: gate GEMM + vec_combined (bf16 MMA) -------------
// A = [ad*vd | an*vn] (K=512), B = Wg. BM=32, BN=64. 4 warps 2x2, warp 16x32.
__global__ __launch_bounds__(128) void gate_mma(
    const float* __restrict__ x,
    const float* __restrict__ Wg, const float* __restrict__ bg,
    const float* __restrict__ alpha_dot, const float* __restrict__ alpha_norm,
    float* __restrict__ out)
{
    __shared__ unsigned As[2][32][20];
    __shared__ unsigned Bs[2][32][36];
    const int t = threadIdx.x, lane = t & 31, wp = t >> 5;
    const int g = lane >> 2, tg = lane & 3;
    const int wm = wp >> 1, wn = wp & 1;
    const int tl = lane >> 3, trow = lane & 7;
    const int aRow  = (tl & 1) * 8 + trow;
    const int aColW = (tl >> 1) * 4;
    const int rb = blockIdx.x * 32;
    const int cb = blockIdx.y * 64;
    const float adv = *alpha_dot, anv = *alpha_norm;

    float C[4][4];
#pragma unroll
    for (int nj = 0; nj < 4; nj++)
#pragma unroll
        for (int e = 0; e < 4; e++) C[nj][e] = 0.f;

#pragma unroll
    for (int i = 0; i < 2; i++) {
        int idx = t + i * 128; int r = idx >> 3, cw = (idx & 7) * 2;
        float4 v = *(const float4*)(g_vd + (size_t)(rb + r) * 256 + cw * 2);
        As[0][r][cw] = pk(adv * v.x, adv * v.y); As[0][r][cw + 1] = pk(adv * v.z, adv * v.w);
    }
#pragma unroll
    for (int i = 0; i < 4; i++) {
        int idx = t + i * 128; int r = idx >> 4, cw = (idx & 15) * 2;
        float4 v = *(const float4*)(Wg + (size_t)r * 256 + cb + cw * 2);
        Bs[0][r][cw] = pk(v.x, v.y); Bs[0][r][cw + 1] = pk(v.z, v.w);
    }
    __syncthreads();

    float4 sA[2], sB[4];
    for (int kc = 0; kc < 16; kc++) {
        const int buf = kc & 1;
        const int k0n = (kc + 1) * 32;
        float scl = 0.f;
        if (kc < 15) {
            const float* src = (k0n < 256) ? g_vd : g_vn;
            scl = (k0n < 256) ? adv : anv;
            const int kk0 = k0n & 255;
#pragma unroll
            for (int i = 0; i < 2; i++) {
                int idx = t + i * 128; int r = idx >> 3, cw = (idx & 7) * 2;
                sA[i] = *(const float4*)(src + (size_t)(rb + r) * 256 + kk0 + cw * 2);
            }
#pragma unroll
            for (int i = 0; i < 4; i++) {
                int idx = t + i * 128; int r = idx >> 4, cw = (idx & 15) * 2;
                sB[i] = *(const float4*)(Wg + (size_t)(k0n + r) * 256 + cb + cw * 2);
            }
        }
#pragma unroll
        for (int kk = 0; kk < 32; kk += 16) {
            const int kkW = kk >> 1;
            unsigned a[4], bfr[2][4];
            ldsm4(a, su(&As[buf][wm * 16 + aRow][aColW + kkW]));
#pragma unroll
            for (int ns = 0; ns < 2; ns++)
                ldsm4t(bfr[ns], su(&Bs[buf][kk + aRow][wn * 16 + ns * 8 + aColW]));
#pragma unroll
            for (int nj = 0; nj < 4; nj++)
                mma_bf16(C[nj], a, &bfr[nj >> 1][(nj & 1) * 2]);
        }
        if (kc < 15) {
            __syncthreads();
            const int nb = buf ^ 1;
#pragma unroll
            for (int i = 0; i < 2; i++) {
                int idx = t + i * 128; int r = idx >> 3, cw = (idx & 7) * 2;
                As[nb][r][cw] = pk(scl * sA[i].x, scl * sA[i].y);
                As[nb][r][cw + 1] = pk(scl * sA[i].z, scl * sA[i].w);
            }
#pragma unroll
            for (int i = 0; i < 4; i++) {
                int idx = t + i * 128; int r = idx >> 4, cw = (idx & 15) * 2;
                Bs[nb][r][cw] = pk(sB[i].x, sB[i].y); Bs[nb][r][cw + 1] = pk(sB[i].z, sB[i].w);
            }
            __syncthreads();
        }
    }
    // epilogue: gate = sigmoid(z); out_vec = gate*vaggr + vec
#pragma unroll
    for (int nj = 0; nj < 4; nj++) {
        int col = cb + wn * 32 + nj * 8 + 2 * tg;
        float bg0 = bg[col], bg1 = bg[col + 1];
#pragma unroll
        for (int hf = 0; hf < 2; hf++) {
            int row = rb + wm * 16 + g + hf * 8;
            int e = hf * 2;
            float g0 = 1.f / (1.f + expf(-(C[nj][e]   + bg0)));
            float g1 = 1.f / (1.f + expf(-(C[nj][e+1] + bg1)));
#pragma unroll
            for (int c = 0; c < 3; c++) {
                float2 va = *(const float2*)(g_vaggr + ((size_t)row * 3 + c) * 256 + col);
                size_t oi = ((size_t)row * 4 + 1 + c) * 256 + col;
                float2 xv = *(const float2*)(x + oi);
                *(float2*)(out + oi) = make_float2(g0 * va.x + xv.x, g1 * va.y + xv.y);
            }
        }
    }
}

// ---------------- launch ----------------------------------------------------
extern "C" void kernel_launch(void* const* d_in, const int* in_sizes, int n_in,
                              void* d_out, int out_size)
{
    const float* x    = (const float*)d_in[0];
    const float* Wq   = (const float*)d_in[1];
    const float* bq   = (const float*)d_in[2];
    const float* Wk   = (const float*)d_in[3];
    const float* bk   = (const float*)d_in[4];
    const float* Wv   = (const float*)d_in[5];
    const float* bv   = (const float*)d_in[6];
    const float* Wo   = (const float*)d_in[7];
    const float* bo   = (const float*)d_in[8];
    const float* Wvec = (const float*)d_in[9];
    const float* ad   = (const float*)d_in[10];
    const float* an   = (const float*)d_in[11];
    const float* Wg   = (const float*)d_in[12];
    const float* bg   = (const float*)d_in[13];
    float* out = (float*)d_out;

    qkv_mma <<<dim3(BN / 64, 12), 128>>>(x, Wq, bq, Wk, bk, Wv, bv);
    vec_mma <<<dim3(BN / 16, 8), 192>>>(x, Wvec);
    attn_kernel<<<dim3(NN / 64, NH, BB), 128>>>(x, out);
    out_mma <<<dim3(BN / 32, 8), 128>>>(Wo, bo, out);
    gate_mma<<<dim3(BN / 32, 4), 128>>>(x, Wg, bg, ad, an, out);
}

// round 9
// speedup vs baseline: 2.7480x; 1.3126x over previous
#include <cuda_runtime.h>
#include <cuda_bf16.h>
#include <math.h>

#define BB   2
#define NN   2048
#define HH   256
#define NH   8
#define HD   32
#define WIN  32
#define WLEN 65
#define BN   (BB*NN)                       /* 4096 rows */
#define AOFF ((size_t)BB*NN*4*HH)          /* x_final elements = 4194304 */

// ---------------- scratch (static device globals; no allocation) ------------
__device__ __align__(16) float g_q[BN*HH];
__device__ __align__(16) float g_k[BN*HH];
__device__ __align__(16) float g_v[BN*HH];
__device__ __align__(16) float g_vd[BN*HH];
__device__ __align__(16) float g_vn[BN*HH];
__device__ __align__(16) float g_xout[BN*HH];
__device__ __align__(16) float g_vaggr[BN*3*HH];

// ---------------- bf16 mma helpers ------------------------------------------
__device__ __forceinline__ unsigned pk(float lo, float hi) {
    unsigned r; asm("cvt.rn.bf16x2.f32 %0, %1, %2;" : "=r"(r) : "f"(hi), "f"(lo));
    return r;
}
__device__ __forceinline__ unsigned su(const void* p) {
    return (unsigned)__cvta_generic_to_shared(p);
}
__device__ __forceinline__ void ldsm4(unsigned* r, unsigned a) {
    asm volatile("ldmatrix.sync.aligned.m8n8.x4.shared.b16 {%0,%1,%2,%3},[%4];"
        : "=r"(r[0]), "=r"(r[1]), "=r"(r[2]), "=r"(r[3]) : "r"(a));
}
__device__ __forceinline__ void ldsm4t(unsigned* r, unsigned a) {
    asm volatile("ldmatrix.sync.aligned.m8n8.x4.trans.shared.b16 {%0,%1,%2,%3},[%4];"
        : "=r"(r[0]), "=r"(r[1]), "=r"(r[2]), "=r"(r[3]) : "r"(a));
}
__device__ __forceinline__ void mma_bf16(float* c, const unsigned* a, const unsigned* b) {
    asm volatile("mma.sync.aligned.m16n8k16.row.col.f32.bf16.bf16.f32 "
        "{%0,%1,%2,%3},{%4,%5,%6,%7},{%8,%9},{%0,%1,%2,%3};"
        : "+f"(c[0]), "+f"(c[1]), "+f"(c[2]), "+f"(c[3])
        : "r"(a[0]), "r"(a[1]), "r"(a[2]), "r"(a[3]), "r"(b[0]), "r"(b[1]));
}

// ---------------- kernel 1: q/k/v projection (bf16 MMA + ldmatrix) ----------
__global__ __launch_bounds__(128) void qkv_mma(
    const float* __restrict__ x,
    const float* __restrict__ Wq, const float* __restrict__ bq,
    const float* __restrict__ Wk, const float* __restrict__ bk,
    const float* __restrict__ Wv, const float* __restrict__ bv)
{
    __shared__ unsigned As[2][64][20];
    __shared__ unsigned Bs[2][32][36];
    const int t = threadIdx.x, lane = t & 31, wp = t >> 5;
    const int g = lane >> 2, tg = lane & 3;
    const int wm = wp >> 1, wn = wp & 1;
    const int tl = lane >> 3, trow = lane & 7;
    const int aRow  = (tl & 1) * 8 + trow;
    const int aColW = (tl >> 1) * 4;
    const int rb = blockIdx.x * 64;
    const int nt = blockIdx.y;
    const float *W, *bias; float* outp;
    if (nt < 4)      { W = Wq; bias = bq; outp = g_q; }
    else if (nt < 8) { W = Wk; bias = bk; outp = g_k; }
    else             { W = Wv; bias = bv; outp = g_v; }
    const int cb = (nt & 3) * 64;

    float C[2][4][4];
#pragma unroll
    for (int mi = 0; mi < 2; mi++)
#pragma unroll
        for (int nj = 0; nj < 4; nj++)
#pragma unroll
            for (int e = 0; e < 4; e++) C[mi][nj][e] = 0.f;

#pragma unroll
    for (int i = 0; i < 4; i++) {
        int idx = t + i * 128; int r = idx >> 3, cw = (idx & 7) * 2;
        float4 v = *(const float4*)(x + (size_t)(rb + r) * 1024 + cw * 2);
        As[0][r][cw] = pk(v.x, v.y); As[0][r][cw + 1] = pk(v.z, v.w);
    }
#pragma unroll
    for (int i = 0; i < 4; i++) {
        int idx = t + i * 128; int r = idx >> 4, cw = (idx & 15) * 2;
        float4 v = *(const float4*)(W + (size_t)r * 256 + cb + cw * 2);
        Bs[0][r][cw] = pk(v.x, v.y); Bs[0][r][cw + 1] = pk(v.z, v.w);
    }
    __syncthreads();

    float4 sA[4], sB[4];
    for (int kc = 0; kc < 8; kc++) {
        const int buf = kc & 1;
        const int k0n = (kc + 1) * 32;
        if (kc < 7) {
#pragma unroll
            for (int i = 0; i < 4; i++) {
                int idx = t + i * 128; int r = idx >> 3, cw = (idx & 7) * 2;
                sA[i] = *(const float4*)(x + (size_t)(rb + r) * 1024 + k0n + cw * 2);
            }
#pragma unroll
            for (int i = 0; i < 4; i++) {
                int idx = t + i * 128; int r = idx >> 4, cw = (idx & 15) * 2;
                sB[i] = *(const float4*)(W + (size_t)(k0n + r) * 256 + cb + cw * 2);
            }
        }
#pragma unroll
        for (int kk = 0; kk < 32; kk += 16) {
            const int kkW = kk >> 1;
            unsigned a[2][4], bfr[2][4];
#pragma unroll
            for (int mi = 0; mi < 2; mi++)
                ldsm4(a[mi], su(&As[buf][wm * 32 + mi * 16 + aRow][aColW + kkW]));
#pragma unroll
            for (int ns = 0; ns < 2; ns++)
                ldsm4t(bfr[ns], su(&Bs[buf][kk + aRow][wn * 16 + ns * 8 + aColW]));
#pragma unroll
            for (int mi = 0; mi < 2; mi++)
#pragma unroll
                for (int nj = 0; nj < 4; nj++)
                    mma_bf16(C[mi][nj], a[mi], &bfr[nj >> 1][(nj & 1) * 2]);
        }
        if (kc < 7) {
            __syncthreads();
            const int nb = buf ^ 1;
#pragma unroll
            for (int i = 0; i < 4; i++) {
                int idx = t + i * 128; int r = idx >> 3, cw = (idx & 7) * 2;
                As[nb][r][cw] = pk(sA[i].x, sA[i].y); As[nb][r][cw + 1] = pk(sA[i].z, sA[i].w);
            }
#pragma unroll
            for (int i = 0; i < 4; i++) {
                int idx = t + i * 128; int r = idx >> 4, cw = (idx & 15) * 2;
                Bs[nb][r][cw] = pk(sB[i].x, sB[i].y); Bs[nb][r][cw + 1] = pk(sB[i].z, sB[i].w);
            }
            __syncthreads();
        }
    }
#pragma unroll
    for (int mi = 0; mi < 2; mi++)
#pragma unroll
        for (int nj = 0; nj < 4; nj++) {
            int row = rb + wm * 32 + mi * 16 + g;
            int col = cb + wn * 32 + nj * 8 + 2 * tg;
            float b0 = bias[col], b1 = bias[col + 1];
            *(float2*)(outp + (size_t)row * 256 + col) =
                make_float2(C[mi][nj][0] + b0, C[mi][nj][1] + b1);
            *(float2*)(outp + (size_t)(row + 8) * 256 + col) =
                make_float2(C[mi][nj][2] + b0, C[mi][nj][3] + b1);
        }
}

// ---------------- kernel 2: vec_proj (bf16 MMA) -> vec_dot; + fp32 vec_norm -
__global__ __launch_bounds__(192) void vec_mma(
    const float* __restrict__ x, const float* __restrict__ Wvec)
{
    __shared__ unsigned As[2][48][20];
    __shared__ unsigned Bs[2][2][32][20];
    __shared__ float pr[48][36];
    const int t = threadIdx.x, lane = t & 31, wp = t >> 5;
    const int g = lane >> 2, tg = lane & 3;
    const int wm = wp % 3, wn = wp / 3;
    const int tl = lane >> 3, trow = lane & 7;
    const int aRow  = (tl & 1) * 8 + trow;
    const int aColW = (tl >> 1) * 4;
    const int rb3 = blockIdx.x * 48, bn0 = blockIdx.x * 16;
    const int n0 = blockIdx.y * 32;

    if (blockIdx.y == 0) {
        for (int idx = t; idx < 16 * 256; idx += 192) {
            int G = idx >> 8, tt = idx & 255;
            size_t base = ((size_t)(bn0 + G) * 4 + 1) * 256 + tt;
            float v0 = x[base], v1 = x[base + 256], v2 = x[base + 512];
            g_vn[(size_t)(bn0 + G) * 256 + tt] = sqrtf(v0*v0 + v1*v1 + v2*v2);
        }
    }

    float C[2][2][4];
#pragma unroll
    for (int s = 0; s < 2; s++)
#pragma unroll
        for (int ni = 0; ni < 2; ni++)
#pragma unroll
            for (int e = 0; e < 4; e++) C[s][ni][e] = 0.f;

#pragma unroll
    for (int i = 0; i < 2; i++) {
        int idx = t + i * 192; int r = idx >> 3, cw = (idx & 7) * 2;
        int R = rb3 + r, bn = R / 3, cch = R - bn * 3;
        float4 v = *(const float4*)(x + ((size_t)bn * 4 + 1 + cch) * 256 + cw * 2);
        As[0][r][cw] = pk(v.x, v.y); As[0][r][cw + 1] = pk(v.z, v.w);
    }
#pragma unroll
    for (int i = 0; i < 3; i++) {
        int idx = t + i * 192;
        if (idx < 512) {
            int s = idx >> 8, rem = idx & 255, r = rem >> 3, cw = (rem & 7) * 2;
            float4 v = *(const float4*)(Wvec + (size_t)r * 512 + s * 256 + n0 + cw * 2);
            Bs[0][s][r][cw] = pk(v.x, v.y); Bs[0][s][r][cw + 1] = pk(v.z, v.w);
        }
    }
    __syncthreads();

    float4 sA[2], sB[3];
    for (int kc = 0; kc < 8; kc++) {
        const int buf = kc & 1;
        const int k0n = (kc + 1) * 32;
        if (kc < 7) {
#pragma unroll
            for (int i = 0; i < 2; i++) {
                int idx = t + i * 192; int r = idx >> 3, cw = (idx & 7) * 2;
                int R = rb3 + r, bn = R / 3, cch = R - bn * 3;
                sA[i] = *(const float4*)(x + ((size_t)bn * 4 + 1 + cch) * 256 + k0n + cw * 2);
            }
#pragma unroll
            for (int i = 0; i < 3; i++) {
                int idx = t + i * 192;
                if (idx < 512) {
                    int s = idx >> 8, rem = idx & 255, r = rem >> 3, cw = (rem & 7) * 2;
                    sB[i] = *(const float4*)(Wvec + (size_t)(k0n + r) * 512 + s * 256 + n0 + cw * 2);
                }
            }
        }
#pragma unroll
        for (int kk = 0; kk < 32; kk += 16) {
            const int kkW = kk >> 1;
            unsigned a[4], bfr[2][4];
            ldsm4(a, su(&As[buf][wm * 16 + aRow][aColW + kkW]));
#pragma unroll
            for (int s = 0; s < 2; s++)
                ldsm4t(bfr[s], su(&Bs[buf][s][kk + aRow][wn * 8 + aColW]));
#pragma unroll
            for (int s = 0; s < 2; s++)
#pragma unroll
                for (int ni = 0; ni < 2; ni++)
                    mma_bf16(C[s][ni], a, &bfr[s][ni * 2]);
        }
        if (kc < 7) {
            __syncthreads();
            const int nb = buf ^ 1;
#pragma unroll
            for (int i = 0; i < 2; i++) {
                int idx = t + i * 192; int r = idx >> 3, cw = (idx & 7) * 2;
                As[nb][r][cw] = pk(sA[i].x, sA[i].y); As[nb][r][cw + 1] = pk(sA[i].z, sA[i].w);
            }
#pragma unroll
            for (int i = 0; i < 3; i++) {
                int idx = t + i * 192;
                if (idx < 512) {
                    int s = idx >> 8, rem = idx & 255, r = rem >> 3, cw = (rem & 7) * 2;
                    Bs[nb][s][r][cw] = pk(sB[i].x, sB[i].y); Bs[nb][s][r][cw + 1] = pk(sB[i].z, sB[i].w);
                }
            }
            __syncthreads();
        }
    }
#pragma unroll
    for (int ni = 0; ni < 2; ni++) {
        int r0 = wm * 16 + g, c0 = wn * 16 + ni * 8 + 2 * tg;
        pr[r0][c0]       = C[0][ni][0] * C[1][ni][0];
        pr[r0][c0 + 1]   = C[0][ni][1] * C[1][ni][1];
        pr[r0 + 8][c0]   = C[0][ni][2] * C[1][ni][2];
        pr[r0 + 8][c0+1] = C[0][ni][3] * C[1][ni][3];
    }
    __syncthreads();
    for (int idx = t; idx < 512; idx += 192) {
        int G = idx >> 5, tt = idx & 31;
        g_vd[(size_t)(bn0 + G) * 256 + n0 + tt] =
            pr[3*G][tt] + pr[3*G+1][tt] + pr[3*G+2][tt];
    }
}

// ---------------- kernel 3: sliding-window attention (restructured) ---------
// grid (N/32, heads, B), 128 threads. Each warp owns 8 queries.
template<bool BND>
__device__ __forceinline__ void attn_agg(
    const float* __restrict__ base, size_t stride, int jq,
    const float (* __restrict__ w)[66], float4* acc)
{
    // ramp-up r = 0..6
#pragma unroll
    for (int r = 0; r < 7; r++) {
        int j = jq + r;
        float4 val = make_float4(0.f, 0.f, 0.f, 0.f);
        if (!BND || (unsigned)j < NN) val = *(const float4*)(base + (size_t)j * stride);
#pragma unroll
        for (int g8 = 0; g8 <= r; g8++) {
            float wv = w[g8][r - g8];
            acc[g8].x = fmaf(wv, val.x, acc[g8].x);
            acc[g8].y = fmaf(wv, val.y, acc[g8].y);
            acc[g8].z = fmaf(wv, val.z, acc[g8].z);
            acc[g8].w = fmaf(wv, val.w, acc[g8].w);
        }
    }
    // main r = 7..64 — predicate-free on window bounds
#pragma unroll 2
    for (int r = 7; r < 65; r++) {
        int j = jq + r;
        float4 val = make_float4(0.f, 0.f, 0.f, 0.f);
        if (!BND || (unsigned)j < NN) val = *(const float4*)(base + (size_t)j * stride);
#pragma unroll
        for (int g8 = 0; g8 < 8; g8++) {
            float wv = w[g8][r - g8];
            acc[g8].x = fmaf(wv, val.x, acc[g8].x);
            acc[g8].y = fmaf(wv, val.y, acc[g8].y);
            acc[g8].z = fmaf(wv, val.z, acc[g8].z);
            acc[g8].w = fmaf(wv, val.w, acc[g8].w);
        }
    }
    // ramp-down r = 65..71
#pragma unroll
    for (int r = 65; r < 72; r++) {
        int j = jq + r;
        float4 val = make_float4(0.f, 0.f, 0.f, 0.f);
        if (!BND || (unsigned)j < NN) val = *(const float4*)(base + (size_t)j * stride);
#pragma unroll
        for (int g8 = r - 64; g8 < 8; g8++) {
            float wv = w[g8][r - g8];
            acc[g8].x = fmaf(wv, val.x, acc[g8].x);
            acc[g8].y = fmaf(wv, val.y, acc[g8].y);
            acc[g8].z = fmaf(wv, val.z, acc[g8].z);
            acc[g8].w = fmaf(wv, val.w, acc[g8].w);
        }
    }
}

__global__ __launch_bounds__(128) void attn_kernel(
    const float* __restrict__ x, float* __restrict__ out)
{
    __shared__ float ks[96][36];       // 16B-aligned rows, conflict-free LDS.128
    __shared__ float qs[32][36];
    __shared__ float ws[4][8][66];
    const int tid  = threadIdx.x;
    const int lane = tid & 31;
    const int wp   = tid >> 5;
    const int i0   = blockIdx.x * 32;
    const int hh   = blockIdx.y;
    const int b    = blockIdx.z;
    const int jb   = i0 - WIN;

    const float* kg = g_k + (size_t)b * NN * HH + hh * HD;
    for (int idx = tid; idx < 96 * 8; idx += 128) {
        int r = idx >> 3, d4 = (idx & 7) * 4, j = jb + r;
        float4 v = make_float4(0.f, 0.f, 0.f, 0.f);
        if ((unsigned)j < NN) v = *(const float4*)(kg + (size_t)j * HH + d4);
        *(float4*)&ks[r][d4] = v;
    }
    const float* qg = g_q + ((size_t)b * NN + i0) * HH + hh * HD;
    for (int idx = tid; idx < 32 * 8; idx += 128) {
        int r = idx >> 3, d4 = (idx & 7) * 4;
        *(float4*)&qs[r][d4] = *(const float4*)(qg + (size_t)r * HH + d4);
    }
    __syncthreads();

    const float scale = 0.17677669529663687f;   // 1/sqrt(32)
    for (int ql = 0; ql < 8; ql++) {
        const int q = wp * 8 + ql;
        const int i = i0 + q;
        float s0 = 0.f, s1 = 0.f;
        {
            const float* qr = qs[q];
            const float* ka = ks[q + lane];
            const float* kb = ks[q + lane + 32];
#pragma unroll
            for (int d4 = 0; d4 < 32; d4 += 4) {
                float4 qv = *(const float4*)(qr + d4);
                float4 a4 = *(const float4*)(ka + d4);
                float4 b4 = *(const float4*)(kb + d4);
                s0 = fmaf(qv.x,a4.x, fmaf(qv.y,a4.y, fmaf(qv.z,a4.z, fmaf(qv.w,a4.w, s0))));
                s1 = fmaf(qv.x,b4.x, fmaf(qv.y,b4.y, fmaf(qv.z,b4.z, fmaf(qv.w,b4.w, s1))));
            }
        }
        float e2 = 0.f;
        if (lane == 0) {
            const float* qr = qs[q];
            const float* kc = ks[q + 64];
            float s2 = 0.f;
#pragma unroll
            for (int d4 = 0; d4 < 32; d4 += 4) {
                float4 qv = *(const float4*)(qr + d4);
                float4 c4 = *(const float4*)(kc + d4);
                s2 = fmaf(qv.x,c4.x, fmaf(qv.y,c4.y, fmaf(qv.z,c4.z, fmaf(qv.w,c4.w, s2))));
            }
            e2 = __expf(s2 * scale);
        }
        // no max-subtraction: |s*scale| is bounded ~O(1), exp(s)/sum identical math
        float e0 = __expf(s0 * scale), e1 = __expf(s1 * scale);
        float sm = e0 + e1 + e2;
#pragma unroll
        for (int o = 16; o; o >>= 1) sm += __shfl_xor_sync(0xffffffffu, sm, o);
        float inv = 1.f / sm;
        float p0 = e0 * inv, p1 = e1 * inv;
        float* ab = out + AOFF + (((size_t)(b * NH + hh)) * NN + i) * WLEN;
        ab[lane]      = p0;
        ab[lane + 32] = p1;
        ws[wp][ql][lane]      = p0;
        ws[wp][ql][lane + 32] = p1;
        if (lane == 0) { float p2 = e2 * inv; ab[64] = p2; ws[wp][ql][64] = p2; }
    }
    __syncwarp();

    // phase 2: aggregation. lane<8 -> v dims; lanes 8..31 -> vec dims.
    const bool isv = (lane < 8);
    int c = 0, ddv = 0;
    if (!isv) { c = (lane - 8) >> 3; ddv = ((lane - 8) & 7) * 4; }
    const size_t stride = isv ? 256 : 1024;
    const float* base = isv
        ? (g_v + (size_t)b * NN * 256 + hh * HD + lane * 4)
        : (x + ((size_t)(b * NN) * 4 + 1 + c) * 256 + hh * HD + ddv);

    const int qb = wp * 8;
    const int jq = jb + qb;
    float4 acc[8];
#pragma unroll
    for (int g8 = 0; g8 < 8; g8++) acc[g8] = make_float4(0.f, 0.f, 0.f, 0.f);

    const bool bound = (jq < 0) || (jq + 71 >= NN);
    if (bound) attn_agg<true >(base, stride, jq, ws[wp], acc);
    else       attn_agg<false>(base, stride, jq, ws[wp], acc);

#pragma unroll
    for (int g8 = 0; g8 < 8; g8++) {
        const int i = i0 + qb + g8;
        if (isv)
            *(float4*)(g_xout + ((size_t)b * NN + i) * 256 + hh * HD + lane * 4) = acc[g8];
        else
            *(float4*)(g_vaggr + (((size_t)(b * NN + i)) * 3 + c) * 256 + hh * HD + ddv) = acc[g8];
    }
}

// ---------------- kernel 4: o = x_out @ Wo + bo ; x_updated (bf16 MMA) ------
__global__ __launch_bounds__(128) void out_mma(
    const float* __restrict__ Wo, const float* __restrict__ bo,
    float* __restrict__ out)
{
    __shared__ unsigned As[2][32][20];
    __shared__ unsigned Bs[2][3][32][20];
    const int t = threadIdx.x, lane = t & 31, wp = t >> 5;
    const int g = lane >> 2, tg = lane & 3;
    const int wm = wp >> 1, wn = wp & 1;
    const int tl = lane >> 3, trow = lane & 7;
    const int aRow  = (tl & 1) * 8 + trow;
    const int aColW = (tl >> 1) * 4;
    const int rb = blockIdx.x * 32;
    const int cb = blockIdx.y * 32;

    float C[3][2][4];
#pragma unroll
    for (int s = 0; s < 3; s++)
#pragma unroll
        for (int ni = 0; ni < 2; ni++)
#pragma unroll
            for (int e = 0; e < 4; e++) C[s][ni][e] = 0.f;

#pragma unroll
    for (int i = 0; i < 2; i++) {
        int idx = t + i * 128; int r = idx >> 3, cw = (idx & 7) * 2;
        float4 v = *(const float4*)(g_xout + (size_t)(rb + r) * 256 + cw * 2);
        As[0][r][cw] = pk(v.x, v.y); As[0][r][cw + 1] = pk(v.z, v.w);
    }
#pragma unroll
    for (int i = 0; i < 6; i++) {
        int idx = t + i * 128;
        int s = idx >> 8, rem = idx & 255, r = rem >> 3, cw = (rem & 7) * 2;
        float4 v = *(const float4*)(Wo + (size_t)r * 768 + s * 256 + cb + cw * 2);
        Bs[0][s][r][cw] = pk(v.x, v.y); Bs[0][s][r][cw + 1] = pk(v.z, v.w);
    }
    __syncthreads();

    float4 sA[2], sB[6];
    for (int kc = 0; kc < 8; kc++) {
        const int buf = kc & 1;
        const int k0n = (kc + 1) * 32;
        if (kc < 7) {
#pragma unroll
            for (int i = 0; i < 2; i++) {
                int idx = t + i * 128; int r = idx >> 3, cw = (idx & 7) * 2;
                sA[i] = *(const float4*)(g_xout + (size_t)(rb + r) * 256 + k0n + cw * 2);
            }
#pragma unroll
            for (int i = 0; i < 6; i++) {
                int idx = t + i * 128;
                int s = idx >> 8, rem = idx & 255, r = rem >> 3, cw = (rem & 7) * 2;
                sB[i] = *(const float4*)(Wo + (size_t)(k0n + r) * 768 + s * 256 + cb + cw * 2);
            }
        }
#pragma unroll
        for (int kk = 0; kk < 32; kk += 16) {
            const int kkW = kk >> 1;
            unsigned a[4], bfr[3][4];
            ldsm4(a, su(&As[buf][wm * 16 + aRow][aColW + kkW]));
#pragma unroll
            for (int s = 0; s < 3; s++)
                ldsm4t(bfr[s], su(&Bs[buf][s][kk + aRow][wn * 8 + aColW]));
#pragma unroll
            for (int s = 0; s < 3; s++)
#pragma unroll
                for (int ni = 0; ni < 2; ni++)
                    mma_bf16(C[s][ni], a, &bfr[s][ni * 2]);
        }
        if (kc < 7) {
            __syncthreads();
            const int nb = buf ^ 1;
#pragma unroll
            for (int i = 0; i < 2; i++) {
                int idx = t + i * 128; int r = idx >> 3, cw = (idx & 7) * 2;
                As[nb][r][cw] = pk(sA[i].x, sA[i].y); As[nb][r][cw + 1] = pk(sA[i].z, sA[i].w);
            }
#pragma unroll
            for (int i = 0; i < 6; i++) {
                int idx = t + i * 128;
                int s = idx >> 8, rem = idx & 255, r = rem >> 3, cw = (rem & 7) * 2;
                Bs[nb][s][r][cw] = pk(sB[i].x, sB[i].y); Bs[nb][s][r][cw + 1] = pk(sB[i].z, sB[i].w);
            }
            __syncthreads();
        }
    }
#pragma unroll
    for (int ni = 0; ni < 2; ni++) {
        int col = cb + wn * 16 + ni * 8 + 2 * tg;
        float b0 = bo[col],       b1 = bo[col + 1];
        float b2 = bo[col + 256], b3 = bo[col + 257];
        float b4 = bo[col + 512], b5 = bo[col + 513];
#pragma unroll
        for (int hf = 0; hf < 2; hf++) {
            int row = rb + wm * 16 + g + hf * 8;
            int e = hf * 2;
            float2 vd = *(const float2*)(g_vd + (size_t)row * 256 + col);
            float2 vn = *(const float2*)(g_vn + (size_t)row * 256 + col);
            float rx = vd.x * (C[0][ni][e]   + b0) + vn.x * (C[1][ni][e]   + b2) + (C[2][ni][e]   + b4);
            float ry = vd.y * (C[0][ni][e+1] + b1) + vn.y * (C[1][ni][e+1] + b3) + (C[2][ni][e+1] + b5);
            *(float2*)(out + (size_t)row * 1024 + col) = make_float2(rx, ry);
        }
    }
}

// ---------------- kernel 5: gate GEMM + vec_combined (bf16 MMA) -------------
__global__ __launch_bounds__(128) void gate_mma(
    const float* __restrict__ x,
    const float* __restrict__ Wg, const float* __restrict__ bg,
    const float* __restrict__ alpha_dot, const float* __restrict__ alpha_norm,
    float* __restrict__ out)
{
    __shared__ unsigned As[2][32][20];
    __shared__ unsigned Bs[2][32][36];
    const int t = threadIdx.x, lane = t & 31, wp = t >> 5;
    const int g = lane >> 2, tg = lane & 3;
    const int wm = wp >> 1, wn = wp & 1;
    const int tl = lane >> 3, trow = lane & 7;
    const int aRow  = (tl & 1) * 8 + trow;
    const int aColW = (tl >> 1) * 4;
    const int rb = blockIdx.x * 32;
    const int cb = blockIdx.y * 64;
    const float adv = *alpha_dot, anv = *alpha_norm;

    float C[4][4];
#pragma unroll
    for (int nj = 0; nj < 4; nj++)
#pragma unroll
        for (int e = 0; e < 4; e++) C[nj][e] = 0.f;

#pragma unroll
    for (int i = 0; i < 2; i++) {
        int idx = t + i * 128; int r = idx >> 3, cw = (idx & 7) * 2;
        float4 v = *(const float4*)(g_vd + (size_t)(rb + r) * 256 + cw * 2);
        As[0][r][cw] = pk(adv * v.x, adv * v.y); As[0][r][cw + 1] = pk(adv * v.z, adv * v.w);
    }
#pragma unroll
    for (int i = 0; i < 4; i++) {
        int idx = t + i * 128; int r = idx >> 4, cw = (idx & 15) * 2;
        float4 v = *(const float4*)(Wg + (size_t)r * 256 + cb + cw * 2);
        Bs[0][r][cw] = pk(v.x, v.y); Bs[0][r][cw + 1] = pk(v.z, v.w);
    }
    __syncthreads();

    float4 sA[2], sB[4];
    for (int kc = 0; kc < 16; kc++) {
        const int buf = kc & 1;
        const int k0n = (kc + 1) * 32;
        float scl = 0.f;
        if (kc < 15) {
            const float* src = (k0n < 256) ? g_vd : g_vn;
            scl = (k0n < 256) ? adv : anv;
            const int kk0 = k0n & 255;
#pragma unroll
            for (int i = 0; i < 2; i++) {
                int idx = t + i * 128; int r = idx >> 3, cw = (idx & 7) * 2;
                sA[i] = *(const float4*)(src + (size_t)(rb + r) * 256 + kk0 + cw * 2);
            }
#pragma unroll
            for (int i = 0; i < 4; i++) {
                int idx = t + i * 128; int r = idx >> 4, cw = (idx & 15) * 2;
                sB[i] = *(const float4*)(Wg + (size_t)(k0n + r) * 256 + cb + cw * 2);
            }
        }
#pragma unroll
        for (int kk = 0; kk < 32; kk += 16) {
            const int kkW = kk >> 1;
            unsigned a[4], bfr[2][4];
            ldsm4(a, su(&As[buf][wm * 16 + aRow][aColW + kkW]));
#pragma unroll
            for (int ns = 0; ns < 2; ns++)
                ldsm4t(bfr[ns], su(&Bs[buf][kk + aRow][wn * 16 + ns * 8 + aColW]));
#pragma unroll
            for (int nj = 0; nj < 4; nj++)
                mma_bf16(C[nj], a, &bfr[nj >> 1][(nj & 1) * 2]);
        }
        if (kc < 15) {
            __syncthreads();
            const int nb = buf ^ 1;
#pragma unroll
            for (int i = 0; i < 2; i++) {
                int idx = t + i * 128; int r = idx >> 3, cw = (idx & 7) * 2;
                As[nb][r][cw] = pk(scl * sA[i].x, scl * sA[i].y);
                As[nb][r][cw + 1] = pk(scl * sA[i].z, scl * sA[i].w);
            }
#pragma unroll
            for (int i = 0; i < 4; i++) {
                int idx = t + i * 128; int r = idx >> 4, cw = (idx & 15) * 2;
                Bs[nb][r][cw] = pk(sB[i].x, sB[i].y); Bs[nb][r][cw + 1] = pk(sB[i].z, sB[i].w);
            }
            __syncthreads();
        }
    }
#pragma unroll
    for (int nj = 0; nj < 4; nj++) {
        int col = cb + wn * 32 + nj * 8 + 2 * tg;
        float bg0 = bg[col], bg1 = bg[col + 1];
#pragma unroll
        for (int hf = 0; hf < 2; hf++) {
            int row = rb + wm * 16 + g + hf * 8;
            int e = hf * 2;
            float g0 = 1.f / (1.f + expf(-(C[nj][e]   + bg0)));
            float g1 = 1.f / (1.f + expf(-(C[nj][e+1] + bg1)));
#pragma unroll
            for (int c = 0; c < 3; c++) {
                float2 va = *(const float2*)(g_vaggr + ((size_t)row * 3 + c) * 256 + col);
                size_t oi = ((size_t)row * 4 + 1 + c) * 256 + col;
                float2 xv = *(const float2*)(x + oi);
                *(float2*)(out + oi) = make_float2(g0 * va.x + xv.x, g1 * va.y + xv.y);
            }
        }
    }
}

// ---------------- launch ----------------------------------------------------
extern "C" void kernel_launch(void* const* d_in, const int* in_sizes, int n_in,
                              void* d_out, int out_size)
{
    const float* x    = (const float*)d_in[0];
    const float* Wq   = (const float*)d_in[1];
    const float* bq   = (const float*)d_in[2];
    const float* Wk   = (const float*)d_in[3];
    const float* bk   = (const float*)d_in[4];
    const float* Wv   = (const float*)d_in[5];
    const float* bv   = (const float*)d_in[6];
    const float* Wo   = (const float*)d_in[7];
    const float* bo   = (const float*)d_in[8];
    const float* Wvec = (const float*)d_in[9];
    const float* ad   = (const float*)d_in[10];
    const float* an   = (const float*)d_in[11];
    const float* Wg   = (const float*)d_in[12];
    const float* bg   = (const float*)d_in[13];
    float* out = (float*)d_out;

    qkv_mma <<<dim3(BN / 64, 12), 128>>>(x, Wq, bq, Wk, bk, Wv, bv);
    vec_mma <<<dim3(BN / 16, 8), 192>>>(x, Wvec);
    attn_kernel<<<dim3(NN / 32, NH, BB), 128>>>(x, out);
    out_mma <<<dim3(BN / 32, 8), 128>>>(Wo, bo, out);
    gate_mma<<<dim3(BN / 32, 4), 128>>>(x, Wg, bg, ad, an, out);
}

// round 10
// speedup vs baseline: 2.8221x; 1.0270x over previous
#include <cuda_runtime.h>
#include <cuda_bf16.h>
#include <math.h>

#define BB   2
#define NN   2048
#define HH   256
#define NH   8
#define HD   32
#define WIN  32
#define WLEN 65
#define BN   (BB*NN)                       /* 4096 rows */
#define AOFF ((size_t)BB*NN*4*HH)          /* x_final elements = 4194304 */

// ---------------- scratch (static device globals; no allocation) ------------
__device__ __align__(16) float g_q[BN*HH];
__device__ __align__(16) float g_k[BN*HH];
__device__ __align__(16) float g_v[BN*HH];
__device__ __align__(16) float g_vd[BN*HH];
__device__ __align__(16) float g_vn[BN*HH];
__device__ __align__(16) float g_xout[BN*HH];
__device__ __align__(16) float g_vaggr[BN*3*HH];

// ---------------- bf16 mma helpers ------------------------------------------
__device__ __forceinline__ unsigned pk(float lo, float hi) {
    unsigned r; asm("cvt.rn.bf16x2.f32 %0, %1, %2;" : "=r"(r) : "f"(hi), "f"(lo));
    return r;
}
__device__ __forceinline__ unsigned su(const void* p) {
    return (unsigned)__cvta_generic_to_shared(p);
}
__device__ __forceinline__ void ldsm4(unsigned* r, unsigned a) {
    asm volatile("ldmatrix.sync.aligned.m8n8.x4.shared.b16 {%0,%1,%2,%3},[%4];"
        : "=r"(r[0]), "=r"(r[1]), "=r"(r[2]), "=r"(r[3]) : "r"(a));
}
__device__ __forceinline__ void ldsm4t(unsigned* r, unsigned a) {
    asm volatile("ldmatrix.sync.aligned.m8n8.x4.trans.shared.b16 {%0,%1,%2,%3},[%4];"
        : "=r"(r[0]), "=r"(r[1]), "=r"(r[2]), "=r"(r[3]) : "r"(a));
}
__device__ __forceinline__ void mma_bf16(float* c, const unsigned* a, const unsigned* b) {
    asm volatile("mma.sync.aligned.m16n8k16.row.col.f32.bf16.bf16.f32 "
        "{%0,%1,%2,%3},{%4,%5,%6,%7},{%8,%9},{%0,%1,%2,%3};"
        : "+f"(c[0]), "+f"(c[1]), "+f"(c[2]), "+f"(c[3])
        : "r"(a[0]), "r"(a[1]), "r"(a[2]), "r"(a[3]), "r"(b[0]), "r"(b[1]));
}

// ---------------- kernel 1: q/k/v projection (bf16 MMA, 256 thr) ------------
// grid (64, 6): y -> weight (y>>1) + 128-col tile ((y&1)*128).
// BM=64, BN=128, BK=32. 8 warps 2(m)x4(n); warp tile 32x32.
__global__ __launch_bounds__(256) void qkv_mma(
    const float* __restrict__ x,
    const float* __restrict__ Wq, const float* __restrict__ bq,
    const float* __restrict__ Wk, const float* __restrict__ bk,
    const float* __restrict__ Wv, const float* __restrict__ bv)
{
    __shared__ unsigned As[2][64][20];      // 64 rows x 32 bf16
    __shared__ unsigned Bs[2][32][68];      // 32 k-rows x 128 bf16 (pad 68 = 17*4)
    const int t = threadIdx.x, lane = t & 31, wp = t >> 5;
    const int g = lane >> 2, tg = lane & 3;
    const int wm = wp >> 2, wn = wp & 3;
    const int tl = lane >> 3, trow = lane & 7;
    const int aRow  = (tl & 1) * 8 + trow;
    const int aColW = (tl >> 1) * 4;
    const int rb = blockIdx.x * 64;
    const int nt = blockIdx.y;
    const float *W, *bias; float* outp;
    if (nt < 2)      { W = Wq; bias = bq; outp = g_q; }
    else if (nt < 4) { W = Wk; bias = bk; outp = g_k; }
    else             { W = Wv; bias = bv; outp = g_v; }
    const int cb = (nt & 1) * 128;

    float C[2][4][4];
#pragma unroll
    for (int mi = 0; mi < 2; mi++)
#pragma unroll
        for (int nj = 0; nj < 4; nj++)
#pragma unroll
            for (int e = 0; e < 4; e++) C[mi][nj][e] = 0.f;

#pragma unroll
    for (int i = 0; i < 2; i++) {
        int idx = t + i * 256; int r = idx >> 3, cw = (idx & 7) * 2;
        float4 v = *(const float4*)(x + (size_t)(rb + r) * 1024 + cw * 2);
        As[0][r][cw] = pk(v.x, v.y); As[0][r][cw + 1] = pk(v.z, v.w);
    }
#pragma unroll
    for (int i = 0; i < 4; i++) {
        int idx = t + i * 256; int r = idx >> 5, cw = (idx & 31) * 2;
        float4 v = *(const float4*)(W + (size_t)r * 256 + cb + cw * 2);
        Bs[0][r][cw] = pk(v.x, v.y); Bs[0][r][cw + 1] = pk(v.z, v.w);
    }
    __syncthreads();

    float4 sA[2], sB[4];
    for (int kc = 0; kc < 8; kc++) {
        const int buf = kc & 1;
        const int k0n = (kc + 1) * 32;
        if (kc < 7) {
#pragma unroll
            for (int i = 0; i < 2; i++) {
                int idx = t + i * 256; int r = idx >> 3, cw = (idx & 7) * 2;
                sA[i] = *(const float4*)(x + (size_t)(rb + r) * 1024 + k0n + cw * 2);
            }
#pragma unroll
            for (int i = 0; i < 4; i++) {
                int idx = t + i * 256; int r = idx >> 5, cw = (idx & 31) * 2;
                sB[i] = *(const float4*)(W + (size_t)(k0n + r) * 256 + cb + cw * 2);
            }
        }
#pragma unroll
        for (int kk = 0; kk < 32; kk += 16) {
            const int kkW = kk >> 1;
            unsigned a[2][4], bfr[2][4];
#pragma unroll
            for (int mi = 0; mi < 2; mi++)
                ldsm4(a[mi], su(&As[buf][wm * 32 + mi * 16 + aRow][aColW + kkW]));
#pragma unroll
            for (int ns = 0; ns < 2; ns++)
                ldsm4t(bfr[ns], su(&Bs[buf][kk + aRow][wn * 16 + ns * 8 + aColW]));
#pragma unroll
            for (int mi = 0; mi < 2; mi++)
#pragma unroll
                for (int nj = 0; nj < 4; nj++)
                    mma_bf16(C[mi][nj], a[mi], &bfr[nj >> 1][(nj & 1) * 2]);
        }
        if (kc < 7) {
            __syncthreads();
            const int nb = buf ^ 1;
#pragma unroll
            for (int i = 0; i < 2; i++) {
                int idx = t + i * 256; int r = idx >> 3, cw = (idx & 7) * 2;
                As[nb][r][cw] = pk(sA[i].x, sA[i].y); As[nb][r][cw + 1] = pk(sA[i].z, sA[i].w);
            }
#pragma unroll
            for (int i = 0; i < 4; i++) {
                int idx = t + i * 256; int r = idx >> 5, cw = (idx & 31) * 2;
                Bs[nb][r][cw] = pk(sB[i].x, sB[i].y); Bs[nb][r][cw + 1] = pk(sB[i].z, sB[i].w);
            }
            __syncthreads();
        }
    }
#pragma unroll
    for (int mi = 0; mi < 2; mi++)
#pragma unroll
        for (int nj = 0; nj < 4; nj++) {
            int row = rb + wm * 32 + mi * 16 + g;
            int col = cb + wn * 32 + nj * 8 + 2 * tg;
            float b0 = bias[col], b1 = bias[col + 1];
            *(float2*)(outp + (size_t)row * 256 + col) =
                make_float2(C[mi][nj][0] + b0, C[mi][nj][1] + b1);
            *(float2*)(outp + (size_t)(row + 8) * 256 + col) =
                make_float2(C[mi][nj][2] + b0, C[mi][nj][3] + b1);
        }
}

// ---------------- kernel 2: vec_proj (bf16 MMA) -> vec_dot; + fp32 vec_norm -
__global__ __launch_bounds__(192) void vec_mma(
    const float* __restrict__ x, const float* __restrict__ Wvec)
{
    __shared__ unsigned As[2][48][20];
    __shared__ unsigned Bs[2][2][32][20];
    __shared__ float pr[48][36];
    const int t = threadIdx.x, lane = t & 31, wp = t >> 5;
    const int g = lane >> 2, tg = lane & 3;
    const int wm = wp % 3, wn = wp / 3;
    const int tl = lane >> 3, trow = lane & 7;
    const int aRow  = (tl & 1) * 8 + trow;
    const int aColW = (tl >> 1) * 4;
    const int rb3 = blockIdx.x * 48, bn0 = blockIdx.x * 16;
    const int n0 = blockIdx.y * 32;

    if (blockIdx.y == 0) {
        for (int idx = t; idx < 16 * 256; idx += 192) {
            int G = idx >> 8, tt = idx & 255;
            size_t base = ((size_t)(bn0 + G) * 4 + 1) * 256 + tt;
            float v0 = x[base], v1 = x[base + 256], v2 = x[base + 512];
            g_vn[(size_t)(bn0 + G) * 256 + tt] = sqrtf(v0*v0 + v1*v1 + v2*v2);
        }
    }

    float C[2][2][4];
#pragma unroll
    for (int s = 0; s < 2; s++)
#pragma unroll
        for (int ni = 0; ni < 2; ni++)
#pragma unroll
            for (int e = 0; e < 4; e++) C[s][ni][e] = 0.f;

#pragma unroll
    for (int i = 0; i < 2; i++) {
        int idx = t + i * 192; int r = idx >> 3, cw = (idx & 7) * 2;
        int R = rb3 + r, bn = R / 3, cch = R - bn * 3;
        float4 v = *(const float4*)(x + ((size_t)bn * 4 + 1 + cch) * 256 + cw * 2);
        As[0][r][cw] = pk(v.x, v.y); As[0][r][cw + 1] = pk(v.z, v.w);
    }
#pragma unroll
    for (int i = 0; i < 3; i++) {
        int idx = t + i * 192;
        if (idx < 512) {
            int s = idx >> 8, rem = idx & 255, r = rem >> 3, cw = (rem & 7) * 2;
            float4 v = *(const float4*)(Wvec + (size_t)r * 512 + s * 256 + n0 + cw * 2);
            Bs[0][s][r][cw] = pk(v.x, v.y); Bs[0][s][r][cw + 1] = pk(v.z, v.w);
        }
    }
    __syncthreads();

    float4 sA[2], sB[3];
    for (int kc = 0; kc < 8; kc++) {
        const int buf = kc & 1;
        const int k0n = (kc + 1) * 32;
        if (kc < 7) {
#pragma unroll
            for (int i = 0; i < 2; i++) {
                int idx = t + i * 192; int r = idx >> 3, cw = (idx & 7) * 2;
                int R = rb3 + r, bn = R / 3, cch = R - bn * 3;
                sA[i] = *(const float4*)(x + ((size_t)bn * 4 + 1 + cch) * 256 + k0n + cw * 2);
            }
#pragma unroll
            for (int i = 0; i < 3; i++) {
                int idx = t + i * 192;
                if (idx < 512) {
                    int s = idx >> 8, rem = idx & 255, r = rem >> 3, cw = (rem & 7) * 2;
                    sB[i] = *(const float4*)(Wvec + (size_t)(k0n + r) * 512 + s * 256 + n0 + cw * 2);
                }
            }
        }
#pragma unroll
        for (int kk = 0; kk < 32; kk += 16) {
            const int kkW = kk >> 1;
            unsigned a[4], bfr[2][4];
            ldsm4(a, su(&As[buf][wm * 16 + aRow][aColW + kkW]));
#pragma unroll
            for (int s = 0; s < 2; s++)
                ldsm4t(bfr[s], su(&Bs[buf][s][kk + aRow][wn * 8 + aColW]));
#pragma unroll
            for (int s = 0; s < 2; s++)
#pragma unroll
                for (int ni = 0; ni < 2; ni++)
                    mma_bf16(C[s][ni], a, &bfr[s][ni * 2]);
        }
        if (kc < 7) {
            __syncthreads();
            const int nb = buf ^ 1;
#pragma unroll
            for (int i = 0; i < 2; i++) {
                int idx = t + i * 192; int r = idx >> 3, cw = (idx & 7) * 2;
                As[nb][r][cw] = pk(sA[i].x, sA[i].y); As[nb][r][cw + 1] = pk(sA[i].z, sA[i].w);
            }
#pragma unroll
            for (int i = 0; i < 3; i++) {
                int idx = t + i * 192;
                if (idx < 512) {
                    int s = idx >> 8, rem = idx & 255, r = rem >> 3, cw = (rem & 7) * 2;
                    Bs[nb][s][r][cw] = pk(sB[i].x, sB[i].y); Bs[nb][s][r][cw + 1] = pk(sB[i].z, sB[i].w);
                }
            }
            __syncthreads();
        }
    }
#pragma unroll
    for (int ni = 0; ni < 2; ni++) {
        int r0 = wm * 16 + g, c0 = wn * 16 + ni * 8 + 2 * tg;
        pr[r0][c0]       = C[0][ni][0] * C[1][ni][0];
        pr[r0][c0 + 1]   = C[0][ni][1] * C[1][ni][1];
        pr[r0 + 8][c0]   = C[0][ni][2] * C[1][ni][2];
        pr[r0 + 8][c0+1] = C[0][ni][3] * C[1][ni][3];
    }
    __syncthreads();
    for (int idx = t; idx < 512; idx += 192) {
        int G = idx >> 5, tt = idx & 31;
        g_vd[(size_t)(bn0 + G) * 256 + n0 + tt] =
            pr[3*G][tt] + pr[3*G+1][tt] + pr[3*G+2][tt];
    }
}

// ---------------- kernel 3: sliding-window attention ------------------------
template<bool BND>
__device__ __forceinline__ void attn_agg(
    const float* __restrict__ base, size_t stride, int jq,
    const float (* __restrict__ w)[66], float4* acc)
{
#pragma unroll
    for (int r = 0; r < 7; r++) {
        int j = jq + r;
        float4 val = make_float4(0.f, 0.f, 0.f, 0.f);
        if (!BND || (unsigned)j < NN) val = *(const float4*)(base + (size_t)j * stride);
#pragma unroll
        for (int g8 = 0; g8 <= r; g8++) {
            float wv = w[g8][r - g8];
            acc[g8].x = fmaf(wv, val.x, acc[g8].x);
            acc[g8].y = fmaf(wv, val.y, acc[g8].y);
            acc[g8].z = fmaf(wv, val.z, acc[g8].z);
            acc[g8].w = fmaf(wv, val.w, acc[g8].w);
        }
    }
#pragma unroll 2
    for (int r = 7; r < 65; r++) {
        int j = jq + r;
        float4 val = make_float4(0.f, 0.f, 0.f, 0.f);
        if (!BND || (unsigned)j < NN) val = *(const float4*)(base + (size_t)j * stride);
#pragma unroll
        for (int g8 = 0; g8 < 8; g8++) {
            float wv = w[g8][r - g8];
            acc[g8].x = fmaf(wv, val.x, acc[g8].x);
            acc[g8].y = fmaf(wv, val.y, acc[g8].y);
            acc[g8].z = fmaf(wv, val.z, acc[g8].z);
            acc[g8].w = fmaf(wv, val.w, acc[g8].w);
        }
    }
#pragma unroll
    for (int r = 65; r < 72; r++) {
        int j = jq + r;
        float4 val = make_float4(0.f, 0.f, 0.f, 0.f);
        if (!BND || (unsigned)j < NN) val = *(const float4*)(base + (size_t)j * stride);
#pragma unroll
        for (int g8 = r - 64; g8 < 8; g8++) {
            float wv = w[g8][r - g8];
            acc[g8].x = fmaf(wv, val.x, acc[g8].x);
            acc[g8].y = fmaf(wv, val.y, acc[g8].y);
            acc[g8].z = fmaf(wv, val.z, acc[g8].z);
            acc[g8].w = fmaf(wv, val.w, acc[g8].w);
        }
    }
}

__global__ __launch_bounds__(128) void attn_kernel(
    const float* __restrict__ x, float* __restrict__ out)
{
    __shared__ float ks[96][36];
    __shared__ float qs[32][36];
    __shared__ float ws[4][8][66];
    const int tid  = threadIdx.x;
    const int lane = tid & 31;
    const int wp   = tid >> 5;
    const int i0   = blockIdx.x * 32;
    const int hh   = blockIdx.y;
    const int b    = blockIdx.z;
    const int jb   = i0 - WIN;

    const float* kg = g_k + (size_t)b * NN * HH + hh * HD;
    for (int idx = tid; idx < 96 * 8; idx += 128) {
        int r = idx >> 3, d4 = (idx & 7) * 4, j = jb + r;
        float4 v = make_float4(0.f, 0.f, 0.f, 0.f);
        if ((unsigned)j < NN) v = *(const float4*)(kg + (size_t)j * HH + d4);
        *(float4*)&ks[r][d4] = v;
    }
    const float* qg = g_q + ((size_t)b * NN + i0) * HH + hh * HD;
    for (int idx = tid; idx < 32 * 8; idx += 128) {
        int r = idx >> 3, d4 = (idx & 7) * 4;
        *(float4*)&qs[r][d4] = *(const float4*)(qg + (size_t)r * HH + d4);
    }
    __syncthreads();

    const float scale = 0.17677669529663687f;
    for (int ql = 0; ql < 8; ql++) {
        const int q = wp * 8 + ql;
        const int i = i0 + q;
        float s0 = 0.f, s1 = 0.f;
        {
            const float* qr = qs[q];
            const float* ka = ks[q + lane];
            const float* kb = ks[q + lane + 32];
#pragma unroll
            for (int d4 = 0; d4 < 32; d4 += 4) {
                float4 qv = *(const float4*)(qr + d4);
                float4 a4 = *(const float4*)(ka + d4);
                float4 b4 = *(const float4*)(kb + d4);
                s0 = fmaf(qv.x,a4.x, fmaf(qv.y,a4.y, fmaf(qv.z,a4.z, fmaf(qv.w,a4.w, s0))));
                s1 = fmaf(qv.x,b4.x, fmaf(qv.y,b4.y, fmaf(qv.z,b4.z, fmaf(qv.w,b4.w, s1))));
            }
        }
        float e2 = 0.f;
        if (lane == 0) {
            const float* qr = qs[q];
            const float* kc = ks[q + 64];
            float s2 = 0.f;
#pragma unroll
            for (int d4 = 0; d4 < 32; d4 += 4) {
                float4 qv = *(const float4*)(qr + d4);
                float4 c4 = *(const float4*)(kc + d4);
                s2 = fmaf(qv.x,c4.x, fmaf(qv.y,c4.y, fmaf(qv.z,c4.z, fmaf(qv.w,c4.w, s2))));
            }
            e2 = __expf(s2 * scale);
        }
        float e0 = __expf(s0 * scale), e1 = __expf(s1 * scale);
        float sm = e0 + e1 + e2;
#pragma unroll
        for (int o = 16; o; o >>= 1) sm += __shfl_xor_sync(0xffffffffu, sm, o);
        float inv = 1.f / sm;
        float p0 = e0 * inv, p1 = e1 * inv;
        float* ab = out + AOFF + (((size_t)(b * NH + hh)) * NN + i) * WLEN;
        ab[lane]      = p0;
        ab[lane + 32] = p1;
        ws[wp][ql][lane]      = p0;
        ws[wp][ql][lane + 32] = p1;
        if (lane == 0) { float p2 = e2 * inv; ab[64] = p2; ws[wp][ql][64] = p2; }
    }
    __syncwarp();

    const bool isv = (lane < 8);
    int c = 0, ddv = 0;
    if (!isv) { c = (lane - 8) >> 3; ddv = ((lane - 8) & 7) * 4; }
    const size_t stride = isv ? 256 : 1024;
    const float* base = isv
        ? (g_v + (size_t)b * NN * 256 + hh * HD + lane * 4)
        : (x + ((size_t)(b * NN) * 4 + 1 + c) * 256 + hh * HD + ddv);

    const int qb = wp * 8;
    const int jq = jb + qb;
    float4 acc[8];
#pragma unroll
    for (int g8 = 0; g8 < 8; g8++) acc[g8] = make_float4(0.f, 0.f, 0.f, 0.f);

    const bool bound = (jq < 0) || (jq + 71 >= NN);
    if (bound) attn_agg<true >(base, stride, jq, ws[wp], acc);
    else       attn_agg<false>(base, stride, jq, ws[wp], acc);

#pragma unroll
    for (int g8 = 0; g8 < 8; g8++) {
        const int i = i0 + qb + g8;
        if (isv)
            *(float4*)(g_xout + ((size_t)b * NN + i) * 256 + hh * HD + lane * 4) = acc[g8];
        else
            *(float4*)(g_vaggr + (((size_t)(b * NN + i)) * 3 + c) * 256 + hh * HD + ddv) = acc[g8];
    }
}

// ---------------- kernel 4: o = x_out @ Wo + bo ; x_updated (256 thr) -------
// BM=64, BN=64 per set, 3 sets. grid (64, 4). 8 warps 2(m)x4(n).
__global__ __launch_bounds__(256) void out_mma(
    const float* __restrict__ Wo, const float* __restrict__ bo,
    float* __restrict__ out)
{
    __shared__ unsigned As[2][64][20];
    __shared__ unsigned Bs[2][3][32][36];
    const int t = threadIdx.x, lane = t & 31, wp = t >> 5;
    const int g = lane >> 2, tg = lane & 3;
    const int wm = wp >> 2, wn = wp & 3;
    const int tl = lane >> 3, trow = lane & 7;
    const int aRow  = (tl & 1) * 8 + trow;
    const int aColW = (tl >> 1) * 4;
    const int rb = blockIdx.x * 64;
    const int cb = blockIdx.y * 64;

    float C[3][2][2][4];
#pragma unroll
    for (int s = 0; s < 3; s++)
#pragma unroll
        for (int mi = 0; mi < 2; mi++)
#pragma unroll
            for (int ni = 0; ni < 2; ni++)
#pragma unroll
                for (int e = 0; e < 4; e++) C[s][mi][ni][e] = 0.f;

#pragma unroll
    for (int i = 0; i < 2; i++) {
        int idx = t + i * 256; int r = idx >> 3, cw = (idx & 7) * 2;
        float4 v = *(const float4*)(g_xout + (size_t)(rb + r) * 256 + cw * 2);
        As[0][r][cw] = pk(v.x, v.y); As[0][r][cw + 1] = pk(v.z, v.w);
    }
#pragma unroll
    for (int i = 0; i < 6; i++) {
        int idx = t + i * 256;
        int s = idx >> 9, rem = idx & 511, r = rem >> 4, cw = (rem & 15) * 2;
        float4 v = *(const float4*)(Wo + (size_t)r * 768 + s * 256 + cb + cw * 2);
        Bs[0][s][r][cw] = pk(v.x, v.y); Bs[0][s][r][cw + 1] = pk(v.z, v.w);
    }
    __syncthreads();

    float4 sA[2], sB[6];
    for (int kc = 0; kc < 8; kc++) {
        const int buf = kc & 1;
        const int k0n = (kc + 1) * 32;
        if (kc < 7) {
#pragma unroll
            for (int i = 0; i < 2; i++) {
                int idx = t + i * 256; int r = idx >> 3, cw = (idx & 7) * 2;
                sA[i] = *(const float4*)(g_xout + (size_t)(rb + r) * 256 + k0n + cw * 2);
            }
#pragma unroll
            for (int i = 0; i < 6; i++) {
                int idx = t + i * 256;
                int s = idx >> 9, rem = idx & 511, r = rem >> 4, cw = (rem & 15) * 2;
                sB[i] = *(const float4*)(Wo + (size_t)(k0n + r) * 768 + s * 256 + cb + cw * 2);
            }
        }
#pragma unroll
        for (int kk = 0; kk < 32; kk += 16) {
            const int kkW = kk >> 1;
            unsigned a[2][4], bfr[3][4];
#pragma unroll
            for (int mi = 0; mi < 2; mi++)
                ldsm4(a[mi], su(&As[buf][wm * 32 + mi * 16 + aRow][aColW + kkW]));
#pragma unroll
            for (int s = 0; s < 3; s++)
                ldsm4t(bfr[s], su(&Bs[buf][s][kk + aRow][wn * 8 + aColW]));
#pragma unroll
            for (int s = 0; s < 3; s++)
#pragma unroll
                for (int mi = 0; mi < 2; mi++)
#pragma unroll
                    for (int ni = 0; ni < 2; ni++)
                        mma_bf16(C[s][mi][ni], a[mi], &bfr[s][ni * 2]);
        }
        if (kc < 7) {
            __syncthreads();
            const int nb = buf ^ 1;
#pragma unroll
            for (int i = 0; i < 2; i++) {
                int idx = t + i * 256; int r = idx >> 3, cw = (idx & 7) * 2;
                As[nb][r][cw] = pk(sA[i].x, sA[i].y); As[nb][r][cw + 1] = pk(sA[i].z, sA[i].w);
            }
#pragma unroll
            for (int i = 0; i < 6; i++) {
                int idx = t + i * 256;
                int s = idx >> 9, rem = idx & 511, r = rem >> 4, cw = (rem & 15) * 2;
                Bs[nb][s][r][cw] = pk(sB[i].x, sB[i].y); Bs[nb][s][r][cw + 1] = pk(sB[i].z, sB[i].w);
            }
            __syncthreads();
        }
    }
    // epilogue: x_updated = vd*o1 + vn*o2 + o3
#pragma unroll
    for (int mi = 0; mi < 2; mi++)
#pragma unroll
        for (int ni = 0; ni < 2; ni++) {
            int col = cb + wn * 16 + ni * 8 + 2 * tg;
            float b0 = bo[col],       b1 = bo[col + 1];
            float b2 = bo[col + 256], b3 = bo[col + 257];
            float b4 = bo[col + 512], b5 = bo[col + 513];
#pragma unroll
            for (int hf = 0; hf < 2; hf++) {
                int row = rb + wm * 32 + mi * 16 + g + hf * 8;
                int e = hf * 2;
                float2 vd = *(const float2*)(g_vd + (size_t)row * 256 + col);
                float2 vn = *(const float2*)(g_vn + (size_t)row * 256 + col);
                float rx = vd.x * (C[0][mi][ni][e]   + b0) + vn.x * (C[1][mi][ni][e]   + b2) + (C[2][mi][ni][e]   + b4);
                float ry = vd.y * (C[0][mi][ni][e+1] + b1) + vn.y * (C[1][mi][ni][e+1] + b3) + (C[2][mi][ni][e+1] + b5);
                *(float2*)(out + (size_t)row * 1024 + col) = make_float2(rx, ry);
            }
        }
}

// ---------------- kernel 5: gate GEMM + vec_combined (256 thr) --------------
// A = [ad*vd | an*vn] (K=512), B = Wg. BM=64, BN=128, grid (64, 2).
// 8 warps 2(m)x4(n), warp 32x32.
__global__ __launch_bounds__(256) void gate_mma(
    const float* __restrict__ x,
    const float* __restrict__ Wg, const float* __restrict__ bg,
    const float* __restrict__ alpha_dot, const float* __restrict__ alpha_norm,
    float* __restrict__ out)
{
    __shared__ unsigned As[2][64][20];
    __shared__ unsigned Bs[2][32][68];
    const int t = threadIdx.x, lane = t & 31, wp = t >> 5;
    const int g = lane >> 2, tg = lane & 3;
    const int wm = wp >> 2, wn = wp & 3;
    const int tl = lane >> 3, trow = lane & 7;
    const int aRow  = (tl & 1) * 8 + trow;
    const int aColW = (tl >> 1) * 4;
    const int rb = blockIdx.x * 64;
    const int cb = blockIdx.y * 128;
    const float adv = *alpha_dot, anv = *alpha_norm;

    float C[2][4][4];
#pragma unroll
    for (int mi = 0; mi < 2; mi++)
#pragma unroll
        for (int nj = 0; nj < 4; nj++)
#pragma unroll
            for (int e = 0; e < 4; e++) C[mi][nj][e] = 0.f;

#pragma unroll
    for (int i = 0; i < 2; i++) {
        int idx = t + i * 256; int r = idx >> 3, cw = (idx & 7) * 2;
        float4 v = *(const float4*)(g_vd + (size_t)(rb + r) * 256 + cw * 2);
        As[0][r][cw] = pk(adv * v.x, adv * v.y); As[0][r][cw + 1] = pk(adv * v.z, adv * v.w);
    }
#pragma unroll
    for (int i = 0; i < 4; i++) {
        int idx = t + i * 256; int r = idx >> 5, cw = (idx & 31) * 2;
        float4 v = *(const float4*)(Wg + (size_t)r * 256 + cb + cw * 2);
        Bs[0][r][cw] = pk(v.x, v.y); Bs[0][r][cw + 1] = pk(v.z, v.w);
    }
    __syncthreads();

    float4 sA[2], sB[4];
    for (int kc = 0; kc < 16; kc++) {
        const int buf = kc & 1;
        const int k0n = (kc + 1) * 32;
        float scl = 0.f;
        if (kc < 15) {
            const float* src = (k0n < 256) ? g_vd : g_vn;
            scl = (k0n < 256) ? adv : anv;
            const int kk0 = k0n & 255;
#pragma unroll
            for (int i = 0; i < 2; i++) {
                int idx = t + i * 256; int r = idx >> 3, cw = (idx & 7) * 2;
                sA[i] = *(const float4*)(src + (size_t)(rb + r) * 256 + kk0 + cw * 2);
            }
#pragma unroll
            for (int i = 0; i < 4; i++) {
                int idx = t + i * 256; int r = idx >> 5, cw = (idx & 31) * 2;
                sB[i] = *(const float4*)(Wg + (size_t)(k0n + r) * 256 + cb + cw * 2);
            }
        }
#pragma unroll
        for (int kk = 0; kk < 32; kk += 16) {
            const int kkW = kk >> 1;
            unsigned a[2][4], bfr[2][4];
#pragma unroll
            for (int mi = 0; mi < 2; mi++)
                ldsm4(a[mi], su(&As[buf][wm * 32 + mi * 16 + aRow][aColW + kkW]));
#pragma unroll
            for (int ns = 0; ns < 2; ns++)
                ldsm4t(bfr[ns], su(&Bs[buf][kk + aRow][wn * 16 + ns * 8 + aColW]));
#pragma unroll
            for (int mi = 0; mi < 2; mi++)
#pragma unroll
                for (int nj = 0; nj < 4; nj++)
                    mma_bf16(C[mi][nj], a[mi], &bfr[nj >> 1][(nj & 1) * 2]);
        }
        if (kc < 15) {
            __syncthreads();
            const int nb = buf ^ 1;
#pragma unroll
            for (int i = 0; i < 2; i++) {
                int idx = t + i * 256; int r = idx >> 3, cw = (idx & 7) * 2;
                As[nb][r][cw] = pk(scl * sA[i].x, scl * sA[i].y);
                As[nb][r][cw + 1] = pk(scl * sA[i].z, scl * sA[i].w);
            }
#pragma unroll
            for (int i = 0; i < 4; i++) {
                int idx = t + i * 256; int r = idx >> 5, cw = (idx & 31) * 2;
                Bs[nb][r][cw] = pk(sB[i].x, sB[i].y); Bs[nb][r][cw + 1] = pk(sB[i].z, sB[i].w);
            }
            __syncthreads();
        }
    }
    // epilogue: gate = sigmoid(z); out_vec = gate*vaggr + vec
#pragma unroll
    for (int mi = 0; mi < 2; mi++)
#pragma unroll
        for (int nj = 0; nj < 4; nj++) {
            int col = cb + wn * 32 + nj * 8 + 2 * tg;
            float bg0 = bg[col], bg1 = bg[col + 1];
#pragma unroll
            for (int hf = 0; hf < 2; hf++) {
                int row = rb + wm * 32 + mi * 16 + g + hf * 8;
                int e = hf * 2;
                float g0 = 1.f / (1.f + expf(-(C[mi][nj][e]   + bg0)));
                float g1 = 1.f / (1.f + expf(-(C[mi][nj][e+1] + bg1)));
#pragma unroll
                for (int c = 0; c < 3; c++) {
                    float2 va = *(const float2*)(g_vaggr + ((size_t)row * 3 + c) * 256 + col);
                    size_t oi = ((size_t)row * 4 + 1 + c) * 256 + col;
                    float2 xv = *(const float2*)(x + oi);
                    *(float2*)(out + oi) = make_float2(g0 * va.x + xv.x, g1 * va.y + xv.y);
                }
            }
        }
}

// ---------------- launch ----------------------------------------------------
extern "C" void kernel_launch(void* const* d_in, const int* in_sizes, int n_in,
                              void* d_out, int out_size)
{
    const float* x    = (const float*)d_in[0];
    const float* Wq   = (const float*)d_in[1];
    const float* bq   = (const float*)d_in[2];
    const float* Wk   = (const float*)d_in[3];
    const float* bk   = (const float*)d_in[4];
    const float* Wv   = (const float*)d_in[5];
    const float* bv   = (const float*)d_in[6];
    const float* Wo   = (const float*)d_in[7];
    const float* bo   = (const float*)d_in[8];
    const float* Wvec = (const float*)d_in[9];
    const float* ad   = (const float*)d_in[10];
    const float* an   = (const float*)d_in[11];
    const float* Wg   = (const float*)d_in[12];
    const float* bg   = (const float*)d_in[13];
    float* out = (float*)d_out;

    qkv_mma <<<dim3(BN / 64, 6), 256>>>(x, Wq, bq, Wk, bk, Wv, bv);
    vec_mma <<<dim3(BN / 16, 8), 192>>>(x, Wvec);
    attn_kernel<<<dim3(NN / 32, NH, BB), 128>>>(x, out);
    out_mma <<<dim3(BN / 64, 4), 256>>>(Wo, bo, out);
    gate_mma<<<dim3(BN / 64, 2), 256>>>(x, Wg, bg, ad, an, out);
}

// round 12
// speedup vs baseline: 2.9190x; 1.0343x over previous
#include <cuda_runtime.h>
#include <cuda_bf16.h>
#include <math.h>

#define BB   2
#define NN   2048
#define HH   256
#define NH   8
#define HD   32
#define WIN  32
#define WLEN 65
#define BN   (BB*NN)                       /* 4096 rows */
#define AOFF ((size_t)BB*NN*4*HH)          /* x_final elements = 4194304 */

// ---------------- scratch (static device globals; no allocation) ------------
__device__ __align__(16) float g_q[BN*HH];
__device__ __align__(16) float g_k[BN*HH];
__device__ __align__(16) float g_v[BN*HH];
__device__ __align__(16) float g_vd[BN*HH];
__device__ __align__(16) float g_vn[BN*HH];
__device__ __align__(16) float g_xout[BN*HH];
__device__ __align__(16) float g_vaggr[BN*3*HH];

// ---------------- bf16 mma helpers ------------------------------------------
__device__ __forceinline__ unsigned pk(float lo, float hi) {
    unsigned r; asm("cvt.rn.bf16x2.f32 %0, %1, %2;" : "=r"(r) : "f"(hi), "f"(lo));
    return r;
}
__device__ __forceinline__ unsigned su(const void* p) {
    return (unsigned)__cvta_generic_to_shared(p);
}
__device__ __forceinline__ void ldsm4(unsigned* r, unsigned a) {
    asm volatile("ldmatrix.sync.aligned.m8n8.x4.shared.b16 {%0,%1,%2,%3},[%4];"
        : "=r"(r[0]), "=r"(r[1]), "=r"(r[2]), "=r"(r[3]) : "r"(a));
}
__device__ __forceinline__ void ldsm4t(unsigned* r, unsigned a) {
    asm volatile("ldmatrix.sync.aligned.m8n8.x4.trans.shared.b16 {%0,%1,%2,%3},[%4];"
        : "=r"(r[0]), "=r"(r[1]), "=r"(r[2]), "=r"(r[3]) : "r"(a));
}
__device__ __forceinline__ void mma_bf16(float* c, const unsigned* a, const unsigned* b) {
    asm volatile("mma.sync.aligned.m16n8k16.row.col.f32.bf16.bf16.f32 "
        "{%0,%1,%2,%3},{%4,%5,%6,%7},{%8,%9},{%0,%1,%2,%3};"
        : "+f"(c[0]), "+f"(c[1]), "+f"(c[2]), "+f"(c[3])
        : "r"(a[0]), "r"(a[1]), "r"(a[2]), "r"(a[3]), "r"(b[0]), "r"(b[1]));
}

// ---------------- smem layout structs ----------------------------------------
struct QkvS { unsigned As[2][64][20]; unsigned Bs[2][32][68]; };     // 27648 B
struct VecS { unsigned As[2][96][20]; unsigned Bs[2][2][32][20]; };  // 25600 B
struct OutS { unsigned As[2][64][20]; unsigned Bs[2][3][32][36]; };  // 37888 B
struct GateS{ unsigned As[2][64][20]; unsigned Bs[2][32][68]; };     // 27648 B

#define PROJ_SMEM (sizeof(QkvS) > sizeof(VecS) ? sizeof(QkvS) : sizeof(VecS))
#define EPI_SMEM  (sizeof(OutS) > sizeof(GateS) ? sizeof(OutS) : sizeof(GateS))

// ---------------- kernel 1: fused projections (qkv + vec_proj/vd/vn) --------
// 1D grid of 1408 blocks, 256 thr.
//   bid <  384 : qkv path — nt=bid/64 (0-1 Wq, 2-3 Wk, 4-5 Wv), rb=(bid%64)*64
//   bid >= 384 : vec path — BM=96 rows (32 groups), BN=32/set x 2 sets
__global__ __launch_bounds__(256) void proj_mma(
    const float* __restrict__ x,
    const float* __restrict__ Wq, const float* __restrict__ bq,
    const float* __restrict__ Wk, const float* __restrict__ bk,
    const float* __restrict__ Wv, const float* __restrict__ bv,
    const float* __restrict__ Wvec)
{
    __shared__ __align__(16) char smraw[PROJ_SMEM];   // fits BOTH path layouts
    const int t = threadIdx.x, lane = t & 31, wp = t >> 5;
    const int g = lane >> 2, tg = lane & 3;
    const int tl = lane >> 3, trow = lane & 7;
    const int aRow  = (tl & 1) * 8 + trow;
    const int aColW = (tl >> 1) * 4;
    const int bid = blockIdx.x;

    if (bid < 384) {
        // ================= qkv path =========
        QkvS& S = *(QkvS*)smraw;
        const int wm = wp >> 2, wn = wp & 3;
        const int nt = bid >> 6;
        const int rb = (bid & 63) * 64;
        const float *W, *bias; float* outp;
        if (nt < 2)      { W = Wq; bias = bq; outp = g_q; }
        else if (nt < 4) { W = Wk; bias = bk; outp = g_k; }
        else             { W = Wv; bias = bv; outp = g_v; }
        const int cb = (nt & 1) * 128;

        float C[2][4][4];
#pragma unroll
        for (int mi = 0; mi < 2; mi++)
#pragma unroll
            for (int nj = 0; nj < 4; nj++)
#pragma unroll
                for (int e = 0; e < 4; e++) C[mi][nj][e] = 0.f;

#pragma unroll
        for (int i = 0; i < 2; i++) {
            int idx = t + i * 256; int r = idx >> 3, cw = (idx & 7) * 2;
            float4 v = *(const float4*)(x + (size_t)(rb + r) * 1024 + cw * 2);
            S.As[0][r][cw] = pk(v.x, v.y); S.As[0][r][cw + 1] = pk(v.z, v.w);
        }
#pragma unroll
        for (int i = 0; i < 4; i++) {
            int idx = t + i * 256; int r = idx >> 5, cw = (idx & 31) * 2;
            float4 v = *(const float4*)(W + (size_t)r * 256 + cb + cw * 2);
            S.Bs[0][r][cw] = pk(v.x, v.y); S.Bs[0][r][cw + 1] = pk(v.z, v.w);
        }
        __syncthreads();

        float4 sA[2], sB[4];
        for (int kc = 0; kc < 8; kc++) {
            const int buf = kc & 1;
            const int k0n = (kc + 1) * 32;
            if (kc < 7) {
#pragma unroll
                for (int i = 0; i < 2; i++) {
                    int idx = t + i * 256; int r = idx >> 3, cw = (idx & 7) * 2;
                    sA[i] = *(const float4*)(x + (size_t)(rb + r) * 1024 + k0n + cw * 2);
                }
#pragma unroll
                for (int i = 0; i < 4; i++) {
                    int idx = t + i * 256; int r = idx >> 5, cw = (idx & 31) * 2;
                    sB[i] = *(const float4*)(W + (size_t)(k0n + r) * 256 + cb + cw * 2);
                }
            }
#pragma unroll
            for (int kk = 0; kk < 32; kk += 16) {
                const int kkW = kk >> 1;
                unsigned a[2][4], bfr[2][4];
#pragma unroll
                for (int mi = 0; mi < 2; mi++)
                    ldsm4(a[mi], su(&S.As[buf][wm * 32 + mi * 16 + aRow][aColW + kkW]));
#pragma unroll
                for (int ns = 0; ns < 2; ns++)
                    ldsm4t(bfr[ns], su(&S.Bs[buf][kk + aRow][wn * 16 + ns * 8 + aColW]));
#pragma unroll
                for (int mi = 0; mi < 2; mi++)
#pragma unroll
                    for (int nj = 0; nj < 4; nj++)
                        mma_bf16(C[mi][nj], a[mi], &bfr[nj >> 1][(nj & 1) * 2]);
            }
            if (kc < 7) {
                __syncthreads();
                const int nb = buf ^ 1;
#pragma unroll
                for (int i = 0; i < 2; i++) {
                    int idx = t + i * 256; int r = idx >> 3, cw = (idx & 7) * 2;
                    S.As[nb][r][cw] = pk(sA[i].x, sA[i].y); S.As[nb][r][cw + 1] = pk(sA[i].z, sA[i].w);
                }
#pragma unroll
                for (int i = 0; i < 4; i++) {
                    int idx = t + i * 256; int r = idx >> 5, cw = (idx & 31) * 2;
                    S.Bs[nb][r][cw] = pk(sB[i].x, sB[i].y); S.Bs[nb][r][cw + 1] = pk(sB[i].z, sB[i].w);
                }
                __syncthreads();
            }
        }
#pragma unroll
        for (int mi = 0; mi < 2; mi++)
#pragma unroll
            for (int nj = 0; nj < 4; nj++) {
                int row = rb + wm * 32 + mi * 16 + g;
                int col = cb + wn * 32 + nj * 8 + 2 * tg;
                float b0 = bias[col], b1 = bias[col + 1];
                *(float2*)(outp + (size_t)row * 256 + col) =
                    make_float2(C[mi][nj][0] + b0, C[mi][nj][1] + b1);
                *(float2*)(outp + (size_t)(row + 8) * 256 + col) =
                    make_float2(C[mi][nj][2] + b0, C[mi][nj][3] + b1);
            }
    } else {
        // ================= vec path: BM=96, 2 sets x 32 cols =================
        VecS& S = *(VecS*)smraw;
        const int vid = bid - 384;
        const int mb = vid >> 3;
        const int n0 = (vid & 7) * 32;
        const int rb3 = mb * 96, bn0 = mb * 32;
        const int wm = wp % 3, wn = wp / 3;     // valid for wp < 6

        // fp32 vec_norm (exact inputs), only the n0==0 slice of blocks
        if (n0 == 0) {
            for (int idx = t; idx < 32 * 256; idx += 256) {
                int G = idx >> 8, tt = idx & 255;
                size_t base = ((size_t)(bn0 + G) * 4 + 1) * 256 + tt;
                float v0 = x[base], v1 = x[base + 256], v2 = x[base + 512];
                g_vn[(size_t)(bn0 + G) * 256 + tt] = sqrtf(v0*v0 + v1*v1 + v2*v2);
            }
        }

        float C[2][2][2][4];                    // [set][mi][ni][4]
#pragma unroll
        for (int s = 0; s < 2; s++)
#pragma unroll
            for (int mi = 0; mi < 2; mi++)
#pragma unroll
                for (int ni = 0; ni < 2; ni++)
#pragma unroll
                    for (int e = 0; e < 4; e++) C[s][mi][ni][e] = 0.f;

#pragma unroll
        for (int i = 0; i < 3; i++) {
            int idx = t + i * 256; int r = idx >> 3, cw = (idx & 7) * 2;
            int R = rb3 + r, bn = R / 3, cch = R - bn * 3;
            float4 v = *(const float4*)(x + ((size_t)bn * 4 + 1 + cch) * 256 + cw * 2);
            S.As[0][r][cw] = pk(v.x, v.y); S.As[0][r][cw + 1] = pk(v.z, v.w);
        }
#pragma unroll
        for (int i = 0; i < 2; i++) {
            int idx = t + i * 256; int s = idx >> 8, rem = idx & 255, r = rem >> 3, cw = (rem & 7) * 2;
            float4 v = *(const float4*)(Wvec + (size_t)r * 512 + s * 256 + n0 + cw * 2);
            S.Bs[0][s][r][cw] = pk(v.x, v.y); S.Bs[0][s][r][cw + 1] = pk(v.z, v.w);
        }
        __syncthreads();

        float4 sA[3], sB[2];
        for (int kc = 0; kc < 8; kc++) {
            const int buf = kc & 1;
            const int k0n = (kc + 1) * 32;
            if (kc < 7) {
#pragma unroll
                for (int i = 0; i < 3; i++) {
                    int idx = t + i * 256; int r = idx >> 3, cw = (idx & 7) * 2;
                    int R = rb3 + r, bn = R / 3, cch = R - bn * 3;
                    sA[i] = *(const float4*)(x + ((size_t)bn * 4 + 1 + cch) * 256 + k0n + cw * 2);
                }
#pragma unroll
                for (int i = 0; i < 2; i++) {
                    int idx = t + i * 256; int s = idx >> 8, rem = idx & 255, r = rem >> 3, cw = (rem & 7) * 2;
                    sB[i] = *(const float4*)(Wvec + (size_t)(k0n + r) * 512 + s * 256 + n0 + cw * 2);
                }
            }
            if (wp < 6) {
#pragma unroll
                for (int kk = 0; kk < 32; kk += 16) {
                    const int kkW = kk >> 1;
                    unsigned a[2][4], bfr[2][4];
#pragma unroll
                    for (int mi = 0; mi < 2; mi++)
                        ldsm4(a[mi], su(&S.As[buf][wm * 32 + mi * 16 + aRow][aColW + kkW]));
#pragma unroll
                    for (int s = 0; s < 2; s++)
                        ldsm4t(bfr[s], su(&S.Bs[buf][s][kk + aRow][wn * 8 + aColW]));
#pragma unroll
                    for (int s = 0; s < 2; s++)
#pragma unroll
                        for (int mi = 0; mi < 2; mi++)
#pragma unroll
                            for (int ni = 0; ni < 2; ni++)
                                mma_bf16(C[s][mi][ni], a[mi], &bfr[s][ni * 2]);
                }
            }
            if (kc < 7) {
                __syncthreads();
                const int nb = buf ^ 1;
#pragma unroll
                for (int i = 0; i < 3; i++) {
                    int idx = t + i * 256; int r = idx >> 3, cw = (idx & 7) * 2;
                    S.As[nb][r][cw] = pk(sA[i].x, sA[i].y); S.As[nb][r][cw + 1] = pk(sA[i].z, sA[i].w);
                }
#pragma unroll
                for (int i = 0; i < 2; i++) {
                    int idx = t + i * 256; int s = idx >> 8, rem = idx & 255, r = rem >> 3, cw = (rem & 7) * 2;
                    S.Bs[nb][s][r][cw] = pk(sB[i].x, sB[i].y); S.Bs[nb][s][r][cw + 1] = pk(sB[i].z, sB[i].w);
                }
                __syncthreads();
            }
        }
        // products vec1*vec2 -> pr (overlays As after a sync), reduce channels
        __syncthreads();
        float (*pr)[33] = (float(*)[33])S.As;   // 96 x 33 floats = 12672 B < 15360 B
        if (wp < 6) {
#pragma unroll
            for (int mi = 0; mi < 2; mi++)
#pragma unroll
                for (int ni = 0; ni < 2; ni++) {
                    int r0 = wm * 32 + mi * 16 + g, c0 = wn * 16 + ni * 8 + 2 * tg;
                    pr[r0][c0]       = C[0][mi][ni][0] * C[1][mi][ni][0];
                    pr[r0][c0 + 1]   = C[0][mi][ni][1] * C[1][mi][ni][1];
                    pr[r0 + 8][c0]   = C[0][mi][ni][2] * C[1][mi][ni][2];
                    pr[r0 + 8][c0+1] = C[0][mi][ni][3] * C[1][mi][ni][3];
                }
        }
        __syncthreads();
        for (int idx = t; idx < 1024; idx += 256) {
            int G = idx >> 5, tt = idx & 31;
            g_vd[(size_t)(bn0 + G) * 256 + n0 + tt] =
                pr[3*G][tt] + pr[3*G+1][tt] + pr[3*G+2][tt];
        }
    }
}

// ---------------- kernel 2: sliding-window attention ------------------------
template<bool BND>
__device__ __forceinline__ void attn_agg(
    const float* __restrict__ base, size_t stride, int jq,
    const float (* __restrict__ w)[66], float4* acc)
{
#pragma unroll
    for (int r = 0; r < 7; r++) {
        int j = jq + r;
        float4 val = make_float4(0.f, 0.f, 0.f, 0.f);
        if (!BND || (unsigned)j < NN) val = *(const float4*)(base + (size_t)j * stride);
#pragma unroll
        for (int g8 = 0; g8 <= r; g8++) {
            float wv = w[g8][r - g8];
            acc[g8].x = fmaf(wv, val.x, acc[g8].x);
            acc[g8].y = fmaf(wv, val.y, acc[g8].y);
            acc[g8].z = fmaf(wv, val.z, acc[g8].z);
            acc[g8].w = fmaf(wv, val.w, acc[g8].w);
        }
    }
#pragma unroll 2
    for (int r = 7; r < 65; r++) {
        int j = jq + r;
        float4 val = make_float4(0.f, 0.f, 0.f, 0.f);
        if (!BND || (unsigned)j < NN) val = *(const float4*)(base + (size_t)j * stride);
#pragma unroll
        for (int g8 = 0; g8 < 8; g8++) {
            float wv = w[g8][r - g8];
            acc[g8].x = fmaf(wv, val.x, acc[g8].x);
            acc[g8].y = fmaf(wv, val.y, acc[g8].y);
            acc[g8].z = fmaf(wv, val.z, acc[g8].z);
            acc[g8].w = fmaf(wv, val.w, acc[g8].w);
        }
    }
#pragma unroll
    for (int r = 65; r < 72; r++) {
        int j = jq + r;
        float4 val = make_float4(0.f, 0.f, 0.f, 0.f);
        if (!BND || (unsigned)j < NN) val = *(const float4*)(base + (size_t)j * stride);
#pragma unroll
        for (int g8 = r - 64; g8 < 8; g8++) {
            float wv = w[g8][r - g8];
            acc[g8].x = fmaf(wv, val.x, acc[g8].x);
            acc[g8].y = fmaf(wv, val.y, acc[g8].y);
            acc[g8].z = fmaf(wv, val.z, acc[g8].z);
            acc[g8].w = fmaf(wv, val.w, acc[g8].w);
        }
    }
}

__global__ __launch_bounds__(128) void attn_kernel(
    const float* __restrict__ x, float* __restrict__ out)
{
    __shared__ float ks[96][36];
    __shared__ float qs[32][36];
    __shared__ float ws[4][8][66];
    const int tid  = threadIdx.x;
    const int lane = tid & 31;
    const int wp   = tid >> 5;
    const int i0   = blockIdx.x * 32;
    const int hh   = blockIdx.y;
    const int b    = blockIdx.z;
    const int jb   = i0 - WIN;

    const float* kg = g_k + (size_t)b * NN * HH + hh * HD;
    for (int idx = tid; idx < 96 * 8; idx += 128) {
        int r = idx >> 3, d4 = (idx & 7) * 4, j = jb + r;
        float4 v = make_float4(0.f, 0.f, 0.f, 0.f);
        if ((unsigned)j < NN) v = *(const float4*)(kg + (size_t)j * HH + d4);
        *(float4*)&ks[r][d4] = v;
    }
    const float* qg = g_q + ((size_t)b * NN + i0) * HH + hh * HD;
    for (int idx = tid; idx < 32 * 8; idx += 128) {
        int r = idx >> 3, d4 = (idx & 7) * 4;
        *(float4*)&qs[r][d4] = *(const float4*)(qg + (size_t)r * HH + d4);
    }
    __syncthreads();

    const float scale = 0.17677669529663687f;
    for (int ql = 0; ql < 8; ql++) {
        const int q = wp * 8 + ql;
        const int i = i0 + q;
        float s0 = 0.f, s1 = 0.f;
        {
            const float* qr = qs[q];
            const float* ka = ks[q + lane];
            const float* kb = ks[q + lane + 32];
#pragma unroll
            for (int d4 = 0; d4 < 32; d4 += 4) {
                float4 qv = *(const float4*)(qr + d4);
                float4 a4 = *(const float4*)(ka + d4);
                float4 b4 = *(const float4*)(kb + d4);
                s0 = fmaf(qv.x,a4.x, fmaf(qv.y,a4.y, fmaf(qv.z,a4.z, fmaf(qv.w,a4.w, s0))));
                s1 = fmaf(qv.x,b4.x, fmaf(qv.y,b4.y, fmaf(qv.z,b4.z, fmaf(qv.w,b4.w, s1))));
            }
        }
        float e2 = 0.f;
        if (lane == 0) {
            const float* qr = qs[q];
            const float* kc = ks[q + 64];
            float s2 = 0.f;
#pragma unroll
            for (int d4 = 0; d4 < 32; d4 += 4) {
                float4 qv = *(const float4*)(qr + d4);
                float4 c4 = *(const float4*)(kc + d4);
                s2 = fmaf(qv.x,c4.x, fmaf(qv.y,c4.y, fmaf(qv.z,c4.z, fmaf(qv.w,c4.w, s2))));
            }
            e2 = __expf(s2 * scale);
        }
        float e0 = __expf(s0 * scale), e1 = __expf(s1 * scale);
        float sm = e0 + e1 + e2;
#pragma unroll
        for (int o = 16; o; o >>= 1) sm += __shfl_xor_sync(0xffffffffu, sm, o);
        float inv = 1.f / sm;
        float p0 = e0 * inv, p1 = e1 * inv;
        float* ab = out + AOFF + (((size_t)(b * NH + hh)) * NN + i) * WLEN;
        ab[lane]      = p0;
        ab[lane + 32] = p1;
        ws[wp][ql][lane]      = p0;
        ws[wp][ql][lane + 32] = p1;
        if (lane == 0) { float p2 = e2 * inv; ab[64] = p2; ws[wp][ql][64] = p2; }
    }
    __syncwarp();

    const bool isv = (lane < 8);
    int c = 0, ddv = 0;
    if (!isv) { c = (lane - 8) >> 3; ddv = ((lane - 8) & 7) * 4; }
    const size_t stride = isv ? 256 : 1024;
    const float* base = isv
        ? (g_v + (size_t)b * NN * 256 + hh * HD + lane * 4)
        : (x + ((size_t)(b * NN) * 4 + 1 + c) * 256 + hh * HD + ddv);

    const int qb = wp * 8;
    const int jq = jb + qb;
    float4 acc[8];
#pragma unroll
    for (int g8 = 0; g8 < 8; g8++) acc[g8] = make_float4(0.f, 0.f, 0.f, 0.f);

    const bool bound = (jq < 0) || (jq + 71 >= NN);
    if (bound) attn_agg<true >(base, stride, jq, ws[wp], acc);
    else       attn_agg<false>(base, stride, jq, ws[wp], acc);

#pragma unroll
    for (int g8 = 0; g8 < 8; g8++) {
        const int i = i0 + qb + g8;
        if (isv)
            *(float4*)(g_xout + ((size_t)b * NN + i) * 256 + hh * HD + lane * 4) = acc[g8];
        else
            *(float4*)(g_vaggr + (((size_t)(b * NN + i)) * 3 + c) * 256 + hh * HD + ddv) = acc[g8];
    }
}

// ---------------- kernel 3: fused epilogue (out ∪ gate) ----------------------
// grid (64, 6), 256 thr. y<4 -> out tile (cb=y*64); y>=4 -> gate tile (cb=(y-4)*128).
__global__ __launch_bounds__(256) void epi_mma(
    const float* __restrict__ x,
    const float* __restrict__ Wo, const float* __restrict__ bo,
    const float* __restrict__ Wg, const float* __restrict__ bg,
    const float* __restrict__ alpha_dot, const float* __restrict__ alpha_norm,
    float* __restrict__ out)
{
    __shared__ __align__(16) char smraw[EPI_SMEM];    // fits BOTH path layouts
    const int t = threadIdx.x, lane = t & 31, wp = t >> 5;
    const int g = lane >> 2, tg = lane & 3;
    const int wm = wp >> 2, wn = wp & 3;
    const int tl = lane >> 3, trow = lane & 7;
    const int aRow  = (tl & 1) * 8 + trow;
    const int aColW = (tl >> 1) * 4;
    const int rb = blockIdx.x * 64;

    if (blockIdx.y < 4) {
        // ================= out path =================
        OutS& S = *(OutS*)smraw;
        const int cb = blockIdx.y * 64;

        float C[3][2][2][4];
#pragma unroll
        for (int s = 0; s < 3; s++)
#pragma unroll
            for (int mi = 0; mi < 2; mi++)
#pragma unroll
                for (int ni = 0; ni < 2; ni++)
#pragma unroll
                    for (int e = 0; e < 4; e++) C[s][mi][ni][e] = 0.f;

#pragma unroll
        for (int i = 0; i < 2; i++) {
            int idx = t + i * 256; int r = idx >> 3, cw = (idx & 7) * 2;
            float4 v = *(const float4*)(g_xout + (size_t)(rb + r) * 256 + cw * 2);
            S.As[0][r][cw] = pk(v.x, v.y); S.As[0][r][cw + 1] = pk(v.z, v.w);
        }
#pragma unroll
        for (int i = 0; i < 6; i++) {
            int idx = t + i * 256;
            int s = idx >> 9, rem = idx & 511, r = rem >> 4, cw = (rem & 15) * 2;
            float4 v = *(const float4*)(Wo + (size_t)r * 768 + s * 256 + cb + cw * 2);
            S.Bs[0][s][r][cw] = pk(v.x, v.y); S.Bs[0][s][r][cw + 1] = pk(v.z, v.w);
        }
        __syncthreads();

        float4 sA[2], sB[6];
        for (int kc = 0; kc < 8; kc++) {
            const int buf = kc & 1;
            const int k0n = (kc + 1) * 32;
            if (kc < 7) {
#pragma unroll
                for (int i = 0; i < 2; i++) {
                    int idx = t + i * 256; int r = idx >> 3, cw = (idx & 7) * 2;
                    sA[i] = *(const float4*)(g_xout + (size_t)(rb + r) * 256 + k0n + cw * 2);
                }
#pragma unroll
                for (int i = 0; i < 6; i++) {
                    int idx = t + i * 256;
                    int s = idx >> 9, rem = idx & 511, r = rem >> 4, cw = (rem & 15) * 2;
                    sB[i] = *(const float4*)(Wo + (size_t)(k0n + r) * 768 + s * 256 + cb + cw * 2);
                }
            }
#pragma unroll
            for (int kk = 0; kk < 32; kk += 16) {
                const int kkW = kk >> 1;
                unsigned a[2][4], bfr[3][4];
#pragma unroll
                for (int mi = 0; mi < 2; mi++)
                    ldsm4(a[mi], su(&S.As[buf][wm * 32 + mi * 16 + aRow][aColW + kkW]));
#pragma unroll
                for (int s = 0; s < 3; s++)
                    ldsm4t(bfr[s], su(&S.Bs[buf][s][kk + aRow][wn * 8 + aColW]));
#pragma unroll
                for (int s = 0; s < 3; s++)
#pragma unroll
                    for (int mi = 0; mi < 2; mi++)
#pragma unroll
                        for (int ni = 0; ni < 2; ni++)
                            mma_bf16(C[s][mi][ni], a[mi], &bfr[s][ni * 2]);
            }
            if (kc < 7) {
                __syncthreads();
                const int nb = buf ^ 1;
#pragma unroll
                for (int i = 0; i < 2; i++) {
                    int idx = t + i * 256; int r = idx >> 3, cw = (idx & 7) * 2;
                    S.As[nb][r][cw] = pk(sA[i].x, sA[i].y); S.As[nb][r][cw + 1] = pk(sA[i].z, sA[i].w);
                }
#pragma unroll
                for (int i = 0; i < 6; i++) {
                    int idx = t + i * 256;
                    int s = idx >> 9, rem = idx & 511, r = rem >> 4, cw = (rem & 15) * 2;
                    S.Bs[nb][s][r][cw] = pk(sB[i].x, sB[i].y); S.Bs[nb][s][r][cw + 1] = pk(sB[i].z, sB[i].w);
                }
                __syncthreads();
            }
        }
#pragma unroll
        for (int mi = 0; mi < 2; mi++)
#pragma unroll
            for (int ni = 0; ni < 2; ni++) {
                int col = cb + wn * 16 + ni * 8 + 2 * tg;
                float b0 = bo[col],       b1 = bo[col + 1];
                float b2 = bo[col + 256], b3 = bo[col + 257];
                float b4 = bo[col + 512], b5 = bo[col + 513];
#pragma unroll
                for (int hf = 0; hf < 2; hf++) {
                    int row = rb + wm * 32 + mi * 16 + g + hf * 8;
                    int e = hf * 2;
                    float2 vd = *(const float2*)(g_vd + (size_t)row * 256 + col);
                    float2 vn = *(const float2*)(g_vn + (size_t)row * 256 + col);
                    float rx = vd.x * (C[0][mi][ni][e]   + b0) + vn.x * (C[1][mi][ni][e]   + b2) + (C[2][mi][ni][e]   + b4);
                    float ry = vd.y * (C[0][mi][ni][e+1] + b1) + vn.y * (C[1][mi][ni][e+1] + b3) + (C[2][mi][ni][e+1] + b5);
                    *(float2*)(out + (size_t)row * 1024 + col) = make_float2(rx, ry);
                }
            }
    } else {
        // ================= gate path =================
        GateS& S = *(GateS*)smraw;
        const int cb = (blockIdx.y - 4) * 128;
        const float adv = *alpha_dot, anv = *alpha_norm;

        float C[2][4][4];
#pragma unroll
        for (int mi = 0; mi < 2; mi++)
#pragma unroll
            for (int nj = 0; nj < 4; nj++)
#pragma unroll
                for (int e = 0; e < 4; e++) C[mi][nj][e] = 0.f;

#pragma unroll
        for (int i = 0; i < 2; i++) {
            int idx = t + i * 256; int r = idx >> 3, cw = (idx & 7) * 2;
            float4 v = *(const float4*)(g_vd + (size_t)(rb + r) * 256 + cw * 2);
            S.As[0][r][cw] = pk(adv * v.x, adv * v.y); S.As[0][r][cw + 1] = pk(adv * v.z, adv * v.w);
        }
#pragma unroll
        for (int i = 0; i < 4; i++) {
            int idx = t + i * 256; int r = idx >> 5, cw = (idx & 31) * 2;
            float4 v = *(const float4*)(Wg + (size_t)r * 256 + cb + cw * 2);
            S.Bs[0][r][cw] = pk(v.x, v.y); S.Bs[0][r][cw + 1] = pk(v.z, v.w);
        }
        __syncthreads();

        float4 sA[2], sB[4];
        for (int kc = 0; kc < 16; kc++) {
            const int buf = kc & 1;
            const int k0n = (kc + 1) * 32;
            float scl = 0.f;
            if (kc < 15) {
                const float* src = (k0n < 256) ? g_vd : g_vn;
                scl = (k0n < 256) ? adv : anv;
                const int kk0 = k0n & 255;
#pragma unroll
                for (int i = 0; i < 2; i++) {
                    int idx = t + i * 256; int r = idx >> 3, cw = (idx & 7) * 2;
                    sA[i] = *(const float4*)(src + (size_t)(rb + r) * 256 + kk0 + cw * 2);
                }
#pragma unroll
                for (int i = 0; i < 4; i++) {
                    int idx = t + i * 256; int r = idx >> 5, cw = (idx & 31) * 2;
                    sB[i] = *(const float4*)(Wg + (size_t)(k0n + r) * 256 + cb + cw * 2);
                }
            }
#pragma unroll
            for (int kk = 0; kk < 32; kk += 16) {
                const int kkW = kk >> 1;
                unsigned a[2][4], bfr[2][4];
#pragma unroll
                for (int mi = 0; mi < 2; mi++)
                    ldsm4(a[mi], su(&S.As[buf][wm * 32 + mi * 16 + aRow][aColW + kkW]));
#pragma unroll
                for (int ns = 0; ns < 2; ns++)
                    ldsm4t(bfr[ns], su(&S.Bs[buf][kk + aRow][wn * 16 + ns * 8 + aColW]));
#pragma unroll
                for (int mi = 0; mi < 2; mi++)
#pragma unroll
                    for (int nj = 0; nj < 4; nj++)
                        mma_bf16(C[mi][nj], a[mi], &bfr[nj >> 1][(nj & 1) * 2]);
            }
            if (kc < 15) {
                __syncthreads();
                const int nb = buf ^ 1;
#pragma unroll
                for (int i = 0; i < 2; i++) {
                    int idx = t + i * 256; int r = idx >> 3, cw = (idx & 7) * 2;
                    S.As[nb][r][cw] = pk(scl * sA[i].x, scl * sA[i].y);
                    S.As[nb][r][cw + 1] = pk(scl * sA[i].z, scl * sA[i].w);
                }
#pragma unroll
                for (int i = 0; i < 4; i++) {
                    int idx = t + i * 256; int r = idx >> 5, cw = (idx & 31) * 2;
                    S.Bs[nb][r][cw] = pk(sB[i].x, sB[i].y); S.Bs[nb][r][cw + 1] = pk(sB[i].z, sB[i].w);
                }
                __syncthreads();
            }
        }
#pragma unroll
        for (int mi = 0; mi < 2; mi++)
#pragma unroll
            for (int nj = 0; nj < 4; nj++) {
                int col = cb + wn * 32 + nj * 8 + 2 * tg;
                float bg0 = bg[col], bg1 = bg[col + 1];
#pragma unroll
                for (int hf = 0; hf < 2; hf++) {
                    int row = rb + wm * 32 + mi * 16 + g + hf * 8;
                    int e = hf * 2;
                    float g0 = 1.f / (1.f + expf(-(C[mi][nj][e]   + bg0)));
                    float g1 = 1.f / (1.f + expf(-(C[mi][nj][e+1] + bg1)));
#pragma unroll
                    for (int c = 0; c < 3; c++) {
                        float2 va = *(const float2*)(g_vaggr + ((size_t)row * 3 + c) * 256 + col);
                        size_t oi = ((size_t)row * 4 + 1 + c) * 256 + col;
                        float2 xv = *(const float2*)(x + oi);
                        *(float2*)(out + oi) = make_float2(g0 * va.x + xv.x, g1 * va.y + xv.y);
                    }
                }
            }
    }
}

// ---------------- launch ----------------------------------------------------
extern "C" void kernel_launch(void* const* d_in, const int* in_sizes, int n_in,
                              void* d_out, int out_size)
{
    const float* x    = (const float*)d_in[0];
    const float* Wq   = (const float*)d_in[1];
    const float* bq   = (const float*)d_in[2];
    const float* Wk   = (const float*)d_in[3];
    const float* bk   = (const float*)d_in[4];
    const float* Wv   = (const float*)d_in[5];
    const float* bv   = (const float*)d_in[6];
    const float* Wo   = (const float*)d_in[7];
    const float* bo   = (const float*)d_in[8];
    const float* Wvec = (const float*)d_in[9];
    const float* ad   = (const float*)d_in[10];
    const float* an   = (const float*)d_in[11];
    const float* Wg   = (const float*)d_in[12];
    const float* bg   = (const float*)d_in[13];
    float* out = (float*)d_out;

    proj_mma<<<384 + 1024, 256>>>(x, Wq, bq, Wk, bk, Wv, bv, Wvec);
    attn_kernel<<<dim3(NN / 32, NH, BB), 128>>>(x, out);
    epi_mma<<<dim3(BN / 64, 6), 256>>>(x, Wo, bo, Wg, bg, ad, an, out);
}